// round 3
// baseline (speedup 1.0000x reference)
#include <cuda_runtime.h>
#include <math.h>
#include <stdint.h>
#include <float.h>

#define B_ 16
#define T_ 2048
#define D_ 512
#define H_ 64

// ---------------- device scratch (no allocations allowed) ----------------
__device__ float4 g_P[B_ * T_];          // 4-momenta
__device__ int    g_len[B_];             // valid lengths per batch
__device__ float  g_mass[B_ * T_ * 3];   // masses for k=2,4,8

// ---------------- f32x2 packed helpers ----------------
__device__ __forceinline__ unsigned long long dup2(float a) {
    unsigned long long r;
    asm("mov.b64 %0, {%1, %1};" : "=l"(r) : "f"(a));
    return r;
}
__device__ __forceinline__ unsigned long long pack2(float lo, float hi) {
    unsigned long long r;
    asm("mov.b64 %0, {%1, %2};" : "=l"(r) : "f"(lo), "f"(hi));
    return r;
}
__device__ __forceinline__ float2 unpack2(unsigned long long v) {
    float2 f;
    asm("mov.b64 {%0, %1}, %2;" : "=f"(f.x), "=f"(f.y) : "l"(v));
    return f;
}
__device__ __forceinline__ unsigned long long fma2(
    unsigned long long a, unsigned long long b, unsigned long long c) {
    unsigned long long d;
    asm("fma.rn.f32x2 %0, %1, %2, %3;" : "=l"(d) : "l"(a), "l"(b), "l"(c));
    return d;
}
__device__ __forceinline__ unsigned long long mul2(
    unsigned long long a, unsigned long long b) {
    unsigned long long d;
    asm("mul.rn.f32x2 %0, %1, %2;" : "=l"(d) : "l"(a), "l"(b));
    return d;
}

// =========================================================================
// Kernel 0: per-batch valid length (mask dtype detected at runtime).
// =========================================================================
__global__ __launch_bounds__(256) void len_kernel(const unsigned char* __restrict__ mask)
{
    int b = blockIdx.x;
    unsigned int w0 = *(const unsigned int*)mask;
    bool byteMode = (w0 == 0x01010101u);   // 1-byte bool layout

    int cnt = 0;
    for (int s = threadIdx.x; s < T_; s += 256) {
        unsigned int mv = byteMode ? (unsigned int)mask[b * T_ + s]
                                   : ((const unsigned int*)mask)[b * T_ + s];
        cnt += (mv != 0u);
    }
    for (int o = 16; o; o >>= 1) cnt += __shfl_down_sync(0xffffffffu, cnt, o);
    __shared__ int sred[8];
    if ((threadIdx.x & 31) == 0) sred[threadIdx.x >> 5] = cnt;
    __syncthreads();
    if (threadIdx.x == 0) {
        int tot = 0;
#pragma unroll
        for (int i = 0; i < 8; i++) tot += sred[i];
        g_len[b] = tot;
    }
}

// =========================================================================
// Kernel 1: 4-momenta. grid = B*T/256 (full-chip spread).
// =========================================================================
__global__ __launch_bounds__(256) void prep_kernel(const float* __restrict__ tokens)
{
    int gt = blockIdx.x * 256 + threadIdx.x;
    float4 tk = ((const float4*)tokens)[gt];
    float E = tk.x, Pt = tk.y, eta = tk.z, phi = tk.w;
    eta = fminf(fmaxf(eta, -20.f), 20.f);
    float sp, cp;
    sincosf(phi, &sp, &cp);
    g_P[gt] = make_float4(E, Pt * cp, Pt * sp, Pt * sinhf(eta));
}

// =========================================================================
// Kernel 2: per-token top-8 Minkowski dot -> masses (k=2,4,8).
// Pass 1: value-only FMNMX top-8. Pass 2: tie-exact A/B index capture.
//   A: d >  th  (at most 7 exist; value+index, ascending s)
//   B: d == th  (index only, first 8 in ascending s)
// Selection = stable-desc-sort(A) ++ B[0 : 8-|A|]  == jax.lax.top_k order.
// =========================================================================
// value-only sorted insert (th0 ascending .. th7); precondition d > th0
#define VINS(dv) do { float c = (dv), t;                  \
    t = fminf(c, th1); c = fmaxf(c, th1); th0 = t;        \
    t = fminf(c, th2); c = fmaxf(c, th2); th1 = t;        \
    t = fminf(c, th3); c = fmaxf(c, th3); th2 = t;        \
    t = fminf(c, th4); c = fmaxf(c, th4); th3 = t;        \
    t = fminf(c, th5); c = fmaxf(c, th5); th4 = t;        \
    t = fminf(c, th6); c = fmaxf(c, th6); th5 = t;        \
    t = fminf(c, th7); c = fmaxf(c, th7); th6 = t;        \
    th7 = c;                                              \
} while (0)

#define CAPTURE(dv, si) do {                                          \
    float _d = (dv);                                                  \
    if (_d >= th) {                                                   \
        if (_d > th) {                                                \
            if (na < 8) { av[na] = _d; ai[na] = (si); na++; }         \
        } else {                                                      \
            if (nb < 8) { bi[nb] = (si); nb++; }                      \
        }                                                             \
    }                                                                 \
} while (0)

__global__ __launch_bounds__(128) void mass_kernel()
{
    __shared__ __align__(16) float sE[T_];
    __shared__ __align__(16) float sX[T_];
    __shared__ __align__(16) float sY[T_];
    __shared__ __align__(16) float sZ[T_];
    __shared__ float sAv[128 * 8];   // strictly-greater candidate values
    __shared__ int   sAi[128 * 8];   // strictly-greater candidate indices
    __shared__ int   sBi[128 * 8];   // equal-to-threshold indices

    int b = blockIdx.y;
    int len = g_len[b];
    const float4* gp = g_P + b * T_;
    for (int i = threadIdx.x; i < T_; i += 128) {
        float4 p = gp[i];
        sE[i] = p.x; sX[i] = p.y; sY[i] = p.z; sZ[i] = p.w;
    }
    __syncthreads();

    int t = blockIdx.x * 128 + threadIdx.x;
    int gt = b * T_ + t;

    if (t >= len) {
        float mv = sqrtf(1e-8f);
        g_mass[gt * 3 + 0] = mv;
        g_mass[gt * 3 + 1] = mv;
        g_mass[gt * 3 + 2] = mv;
        return;
    }

    float aE = sE[t], ax = -sX[t], ay = -sY[t], az = -sZ[t];  // metric folded
    unsigned long long aE2 = dup2(aE), ax2 = dup2(ax), ay2 = dup2(ay), az2 = dup2(az);

    float th0 = -FLT_MAX, th1 = -FLT_MAX, th2 = -FLT_MAX, th3 = -FLT_MAX;
    float th4 = -FLT_MAX, th5 = -FLT_MAX, th6 = -FLT_MAX, th7 = -FLT_MAX;

    int len4 = len & ~3;

    // ---- pass 1: top-8 values ----
    for (int s = 0; s < len4; s += 4) {
        ulonglong2 E4 = *(const ulonglong2*)&sE[s];
        ulonglong2 X4 = *(const ulonglong2*)&sX[s];
        ulonglong2 Y4 = *(const ulonglong2*)&sY[s];
        ulonglong2 Z4 = *(const ulonglong2*)&sZ[s];
        unsigned long long dA2 = fma2(aE2, E4.x, fma2(ax2, X4.x, fma2(ay2, Y4.x, mul2(az2, Z4.x))));
        unsigned long long dB2 = fma2(aE2, E4.y, fma2(ax2, X4.y, fma2(ay2, Y4.y, mul2(az2, Z4.y))));
        float2 dA = unpack2(dA2);
        float2 dB = unpack2(dB2);
        if (fmaxf(dA.x, dA.y) > th0) {
            if (dA.x > th0) VINS(dA.x);
            if (dA.y > th0) VINS(dA.y);
        }
        if (fmaxf(dB.x, dB.y) > th0) {
            if (dB.x > th0) VINS(dB.x);
            if (dB.y > th0) VINS(dB.y);
        }
    }
    for (int s = len4; s < len; s++) {
        float d = fmaf(aE, sE[s], fmaf(ax, sX[s], fmaf(ay, sY[s], az * sZ[s])));
        if (d > th0) VINS(d);
    }

    // ---- pass 2: tie-exact capture of indices ----
    float th = th0;
    float* av = &sAv[threadIdx.x * 8];
    int*   ai = &sAi[threadIdx.x * 8];
    int*   bi = &sBi[threadIdx.x * 8];
    int na = 0, nb = 0;

    for (int s = 0; s < len4; s += 4) {
        ulonglong2 E4 = *(const ulonglong2*)&sE[s];
        ulonglong2 X4 = *(const ulonglong2*)&sX[s];
        ulonglong2 Y4 = *(const ulonglong2*)&sY[s];
        ulonglong2 Z4 = *(const ulonglong2*)&sZ[s];
        unsigned long long dA2 = fma2(aE2, E4.x, fma2(ax2, X4.x, fma2(ay2, Y4.x, mul2(az2, Z4.x))));
        unsigned long long dB2 = fma2(aE2, E4.y, fma2(ax2, X4.y, fma2(ay2, Y4.y, mul2(az2, Z4.y))));
        float2 dA = unpack2(dA2);
        float2 dB = unpack2(dB2);
        if (fmaxf(dA.x, dA.y) >= th) {
            CAPTURE(dA.x, s);
            CAPTURE(dA.y, s + 1);
        }
        if (fmaxf(dB.x, dB.y) >= th) {
            CAPTURE(dB.x, s + 2);
            CAPTURE(dB.y, s + 3);
        }
    }
    for (int s = len4; s < len; s++) {
        float d = fmaf(aE, sE[s], fmaf(ax, sX[s], fmaf(ay, sY[s], az * sZ[s])));
        CAPTURE(d, s);
    }

    // ---- stable sort A descending by value (capture order = asc index) ----
    float v[8]; int idA[8];
#pragma unroll
    for (int j = 0; j < 8; j++) {
        v[j]   = (j < na) ? av[j] : -FLT_MAX;
        idA[j] = (j < na) ? ai[j] : 0;
    }
#pragma unroll
    for (int i = 0; i < 7; i++) {
#pragma unroll
        for (int j = 0; j < 7 - i; j++) {
            bool p = v[j + 1] > v[j];   // strict -> stable
            float hv = p ? v[j + 1] : v[j];
            float lv = p ? v[j] : v[j + 1];
            int hi_ = p ? idA[j + 1] : idA[j];
            int lo_ = p ? idA[j] : idA[j + 1];
            v[j] = hv; v[j + 1] = lv; idA[j] = hi_; idA[j + 1] = lo_;
        }
    }

    // ---- merge: A (desc) then ties B (asc index) ----
    int id[8];
#pragma unroll
    for (int j = 0; j < 8; j++) {
        int jb = j - na;
        jb = jb < 0 ? 0 : (jb > 7 ? 7 : jb);
        id[j] = (j < na) ? idA[j] : bi[jb];
    }

    // ---- cumsum of selected 4-momenta in top_k order -> masses ----
    float cE = 0.f, cX = 0.f, cY = 0.f, cZ = 0.f;
    float m[3];
    int kk = 0;
#pragma unroll
    for (int j = 0; j < 8; j++) {
        int ix = id[j];
        cE += sE[ix]; cX += sX[ix]; cY += sY[ix]; cZ += sZ[ix];
        if (j == 1 || j == 3 || j == 7) {
            float m2 = fmaf(cE, cE, -fmaf(cX, cX, fmaf(cY, cY, cZ * cZ)));
            m[kk++] = sqrtf(fmaxf(m2, 0.f) + 1e-8f);
        }
    }
    g_mass[gt * 3 + 0] = m[0];
    g_mass[gt * 3 + 1] = m[1];
    g_mass[gt * 3 + 2] = m[2];
}

// =========================================================================
// Kernel 3: MLP  out = gelu(mass@W1 + b1) @ W2 + b2   (fp32, FFMA2-packed)
// =========================================================================
__global__ __launch_bounds__(128) void mlp_kernel(
    const float* __restrict__ W1, const float* __restrict__ b1,
    const float* __restrict__ W2, const float* __restrict__ b2,
    float* __restrict__ out)
{
    __shared__ __align__(16) float sA[H_][64];    // h transposed: [hidden][token]
    __shared__ __align__(16) float sB[H_][128];   // W2 chunk

    int tok0 = blockIdx.x * 64;
    int tid = threadIdx.x;

    // --- compute h (gelu exact) into sA ---
    {
        int tt = tid & 63;
        int gt = tok0 + tt;
        float m0 = g_mass[gt * 3 + 0];
        float m1 = g_mass[gt * 3 + 1];
        float m2v = g_mass[gt * 3 + 2];
        for (int j = (tid >> 6); j < H_; j += 2) {
            float x = fmaf(m0, W1[j], fmaf(m1, W1[H_ + j], fmaf(m2v, W1[2 * H_ + j], b1[j])));
            float h = 0.5f * x * (1.f + erff(x * 0.70710678118654752f));
            sA[j][tt] = h;
        }
    }

    int tc = tid & 15;   // column group (8 cols each)
    int tr = tid >> 4;   // token group (8 tokens each)

    for (int nc = 0; nc < 4; nc++) {
        __syncthreads();
        for (int i = tid; i < (H_ * 128) / 4; i += 128) {
            int k = i >> 5;
            int c4 = i & 31;
            ((float4*)(&sB[k][0]))[c4] =
                ((const float4*)(W2 + k * D_ + nc * 128))[c4];
        }
        __syncthreads();

        unsigned long long acc[8][4];
        {
            const float4 bb0 = *(const float4*)(b2 + nc * 128 + tc * 8);
            const float4 bb1 = *(const float4*)(b2 + nc * 128 + tc * 8 + 4);
            unsigned long long c0 = pack2(bb0.x, bb0.y);
            unsigned long long c1 = pack2(bb0.z, bb0.w);
            unsigned long long c2 = pack2(bb1.x, bb1.y);
            unsigned long long c3 = pack2(bb1.z, bb1.w);
#pragma unroll
            for (int ti = 0; ti < 8; ti++) {
                acc[ti][0] = c0; acc[ti][1] = c1; acc[ti][2] = c2; acc[ti][3] = c3;
            }
        }

#pragma unroll 8
        for (int k = 0; k < H_; k++) {
            float4 a0 = *(const float4*)&sA[k][tr * 8];
            float4 a1 = *(const float4*)&sA[k][tr * 8 + 4];
            ulonglong2 bv0 = *(const ulonglong2*)&sB[k][tc * 8];
            ulonglong2 bv1 = *(const ulonglong2*)&sB[k][tc * 8 + 4];
            float avv[8] = {a0.x, a0.y, a0.z, a0.w, a1.x, a1.y, a1.z, a1.w};
#pragma unroll
            for (int ti = 0; ti < 8; ti++) {
                unsigned long long ad = dup2(avv[ti]);
                acc[ti][0] = fma2(ad, bv0.x, acc[ti][0]);
                acc[ti][1] = fma2(ad, bv0.y, acc[ti][1]);
                acc[ti][2] = fma2(ad, bv1.x, acc[ti][2]);
                acc[ti][3] = fma2(ad, bv1.y, acc[ti][3]);
            }
        }

#pragma unroll
        for (int ti = 0; ti < 8; ti++) {
            float2 f0 = unpack2(acc[ti][0]);
            float2 f1 = unpack2(acc[ti][1]);
            float2 f2 = unpack2(acc[ti][2]);
            float2 f3 = unpack2(acc[ti][3]);
            float4 o0 = make_float4(f0.x, f0.y, f1.x, f1.y);
            float4 o1 = make_float4(f2.x, f2.y, f3.x, f3.y);
            float* op = out + (size_t)(tok0 + tr * 8 + ti) * D_ + nc * 128 + tc * 8;
            *(float4*)op = o0;
            *((float4*)op + 1) = o1;
        }
    }
}

// =========================================================================
extern "C" void kernel_launch(void* const* d_in, const int* in_sizes, int n_in,
                              void* d_out, int out_size)
{
    const float* tokens        = (const float*)d_in[0];
    const unsigned char* mask  = (const unsigned char*)d_in[1];
    const float* W1            = (const float*)d_in[2];
    const float* b1            = (const float*)d_in[3];
    const float* W2            = (const float*)d_in[4];
    const float* b2            = (const float*)d_in[5];
    float* out                 = (float*)d_out;

    len_kernel<<<B_, 256>>>(mask);
    prep_kernel<<<(B_ * T_) / 256, 256>>>(tokens);
    mass_kernel<<<dim3(T_ / 128, B_), 128>>>();
    mlp_kernel<<<(B_ * T_) / 64, 128>>>(W1, b1, W2, b2, out);
}

// round 5
// speedup vs baseline: 1.1112x; 1.1112x over previous
#include <cuda_runtime.h>
#include <math.h>
#include <stdint.h>
#include <float.h>

#define B_ 16
#define T_ 2048
#define D_ 512
#define H_ 64

typedef unsigned long long u64;

// ---------------- device scratch (no allocations allowed) ----------------
__device__ float4 g_P[B_ * T_];          // 4-momenta
__device__ int    g_len[B_];             // valid lengths per batch
__device__ float  g_mass[B_ * T_ * 3];   // masses for k=2,4,8
__device__ float  g_mrow[D_];            // output row for masked tokens

// ---------------- f32x2 packed helpers ----------------
__device__ __forceinline__ u64 dup2(float a) {
    u64 r; asm("mov.b64 %0, {%1, %1};" : "=l"(r) : "f"(a)); return r;
}
__device__ __forceinline__ u64 pack2(float lo, float hi) {
    u64 r; asm("mov.b64 %0, {%1, %2};" : "=l"(r) : "f"(lo), "f"(hi)); return r;
}
__device__ __forceinline__ float2 unpack2(u64 v) {
    float2 f; asm("mov.b64 {%0, %1}, %2;" : "=f"(f.x), "=f"(f.y) : "l"(v)); return f;
}
__device__ __forceinline__ u64 fma2(u64 a, u64 b, u64 c) {
    u64 d; asm("fma.rn.f32x2 %0, %1, %2, %3;" : "=l"(d) : "l"(a), "l"(b), "l"(c)); return d;
}
__device__ __forceinline__ u64 mul2(u64 a, u64 b) {
    u64 d; asm("mul.rn.f32x2 %0, %1, %2;" : "=l"(d) : "l"(a), "l"(b)); return d;
}
__device__ __forceinline__ float gelu(float x) {
    return 0.5f * x * (1.f + erff(x * 0.70710678118654752f));
}

// =========================================================================
// Kernel 0: per-batch valid length (mask dtype detected at runtime).
// =========================================================================
__global__ __launch_bounds__(256) void len_kernel(const unsigned char* __restrict__ mask)
{
    int b = blockIdx.x;
    unsigned int w0 = *(const unsigned int*)mask;
    bool byteMode = (w0 == 0x01010101u);

    int cnt = 0;
    for (int s = threadIdx.x; s < T_; s += 256) {
        unsigned int mv = byteMode ? (unsigned int)mask[b * T_ + s]
                                   : ((const unsigned int*)mask)[b * T_ + s];
        cnt += (mv != 0u);
    }
    for (int o = 16; o; o >>= 1) cnt += __shfl_down_sync(0xffffffffu, cnt, o);
    __shared__ int sred[8];
    if ((threadIdx.x & 31) == 0) sred[threadIdx.x >> 5] = cnt;
    __syncthreads();
    if (threadIdx.x == 0) {
        int tot = 0;
#pragma unroll
        for (int i = 0; i < 8; i++) tot += sred[i];
        g_len[b] = tot;
    }
}

// =========================================================================
// Kernel 1: 4-momenta.
// =========================================================================
__global__ __launch_bounds__(256) void prep_kernel(const float* __restrict__ tokens)
{
    int gt = blockIdx.x * 256 + threadIdx.x;
    float4 tk = ((const float4*)tokens)[gt];
    float E = tk.x, Pt = tk.y, eta = tk.z, phi = tk.w;
    eta = fminf(fmaxf(eta, -20.f), 20.f);
    float sp, cp;
    sincosf(phi, &sp, &cp);
    g_P[gt] = make_float4(E, Pt * cp, Pt * sp, Pt * sinhf(eta));
}

// =========================================================================
// Kernel 1b: output row for masked tokens (all masses == sqrt(1e-8)).
// =========================================================================
__global__ __launch_bounds__(512) void mrow_kernel(
    const float* __restrict__ W1, const float* __restrict__ b1,
    const float* __restrict__ W2, const float* __restrict__ b2)
{
    __shared__ float hm[H_];
    int tid = threadIdx.x;
    float mv = sqrtf(1e-8f);
    if (tid < H_) {
        float x = fmaf(mv, W1[tid], fmaf(mv, W1[H_ + tid], fmaf(mv, W1[2 * H_ + tid], b1[tid])));
        hm[tid] = gelu(x);
    }
    __syncthreads();
    float acc = b2[tid];
#pragma unroll 16
    for (int k = 0; k < H_; k++) acc = fmaf(hm[k], W2[k * D_ + tid], acc);
    g_mrow[tid] = acc;
}

// =========================================================================
// Kernel 2: per-token top-8 Minkowski dot -> masses (k=2,4,8).
// Block = 32 tokens (lane <-> token), 4 warps each scan a quarter of [0,len).
// Per quarter: pass1 value-only FMNMX top-8, pass2 tie-exact A/B capture.
// Warp 0 then 4-way-merges the quarter lists (value desc, quarter asc on
// ties == global index asc) and does the cumsum -> masses.
// =========================================================================
#define VINS(dv) do { float c = (dv), t;                  \
    t = fminf(c, th1); c = fmaxf(c, th1); th0 = t;        \
    t = fminf(c, th2); c = fmaxf(c, th2); th1 = t;        \
    t = fminf(c, th3); c = fmaxf(c, th3); th2 = t;        \
    t = fminf(c, th4); c = fmaxf(c, th4); th3 = t;        \
    t = fminf(c, th5); c = fmaxf(c, th5); th4 = t;        \
    t = fminf(c, th6); c = fmaxf(c, th6); th5 = t;        \
    t = fminf(c, th7); c = fmaxf(c, th7); th6 = t;        \
    th7 = c;                                              \
} while (0)

#define CAPTURE(dv, si) do {                                          \
    float _d = (dv);                                                  \
    if (_d >= th) {                                                   \
        if (_d > th) {                                                \
            if (na < 8) { av[na] = _d; ai[na] = (si); na++; }         \
        } else {                                                      \
            if (nb < 8) { bi[nb] = (si); nb++; }                      \
        }                                                             \
    }                                                                 \
} while (0)

__global__ __launch_bounds__(128) void mass_kernel()
{
    __shared__ __align__(16) float sE[T_];
    __shared__ __align__(16) float sX[T_];
    __shared__ __align__(16) float sY[T_];
    __shared__ __align__(16) float sZ[T_];
    __shared__ __align__(16) float sAv[128 * 8];  // pass2 A values; reused as final lists
    __shared__ __align__(16) int   sAi[128 * 8];  // pass2 A indices; reused as final lists
    __shared__ __align__(16) int   sBi[128 * 8];  // pass2 tie indices

    int b = blockIdx.y;
    int len = g_len[b];
    int tbase = blockIdx.x * 32;
    int tid = threadIdx.x, lane = tid & 31, w = tid >> 5;
    float mv = sqrtf(1e-8f);

    if (tbase >= len) {                 // whole block masked
        if (tid < 96) g_mass[(b * T_ + tbase) * 3 + tid] = mv;
        return;
    }

    const float4* gp = g_P + b * T_;
    for (int i = tid; i < T_; i += 128) {
        float4 p = gp[i];
        sE[i] = p.x; sX[i] = p.y; sY[i] = p.z; sZ[i] = p.w;
    }
    __syncthreads();

    int t = tbase + lane;
    int q0 = (w * len) >> 2;
    int q1 = ((w + 1) * len) >> 2;

    float aE = sE[t], ax = -sX[t], ay = -sY[t], az = -sZ[t];  // metric folded
    u64 aE2 = dup2(aE), ax2 = dup2(ax), ay2 = dup2(ay), az2 = dup2(az);

    float th0 = -FLT_MAX, th1 = -FLT_MAX, th2 = -FLT_MAX, th3 = -FLT_MAX;
    float th4 = -FLT_MAX, th5 = -FLT_MAX, th6 = -FLT_MAX, th7 = -FLT_MAX;

    int s0 = (q0 + 3) & ~3; if (s0 > q1) s0 = q1;
    int s1 = q1 & ~3;       if (s1 < s0) s1 = s0;

    // ---- pass 1: quarter-local top-8 values ----
    for (int s = q0; s < s0; s++) {
        float d = fmaf(aE, sE[s], fmaf(ax, sX[s], fmaf(ay, sY[s], az * sZ[s])));
        if (d > th0) VINS(d);
    }
    for (int s = s0; s < s1; s += 4) {
        ulonglong2 E4 = *(const ulonglong2*)&sE[s];
        ulonglong2 X4 = *(const ulonglong2*)&sX[s];
        ulonglong2 Y4 = *(const ulonglong2*)&sY[s];
        ulonglong2 Z4 = *(const ulonglong2*)&sZ[s];
        u64 dA2 = fma2(aE2, E4.x, fma2(ax2, X4.x, fma2(ay2, Y4.x, mul2(az2, Z4.x))));
        u64 dB2 = fma2(aE2, E4.y, fma2(ax2, X4.y, fma2(ay2, Y4.y, mul2(az2, Z4.y))));
        float2 dA = unpack2(dA2);
        float2 dB = unpack2(dB2);
        if (fmaxf(fmaxf(dA.x, dA.y), fmaxf(dB.x, dB.y)) > th0) {
            if (dA.x > th0) VINS(dA.x);
            if (dA.y > th0) VINS(dA.y);
            if (dB.x > th0) VINS(dB.x);
            if (dB.y > th0) VINS(dB.y);
        }
    }
    for (int s = s1; s < q1; s++) {
        float d = fmaf(aE, sE[s], fmaf(ax, sX[s], fmaf(ay, sY[s], az * sZ[s])));
        if (d > th0) VINS(d);
    }

    // ---- pass 2: tie-exact index capture in ascending s ----
    float th = th0;
    float* av = &sAv[tid * 8];
    int*   ai = &sAi[tid * 8];
    int*   bi = &sBi[tid * 8];
    int na = 0, nb = 0;

    for (int s = q0; s < s0; s++) {
        float d = fmaf(aE, sE[s], fmaf(ax, sX[s], fmaf(ay, sY[s], az * sZ[s])));
        CAPTURE(d, s);
    }
    for (int s = s0; s < s1; s += 4) {
        ulonglong2 E4 = *(const ulonglong2*)&sE[s];
        ulonglong2 X4 = *(const ulonglong2*)&sX[s];
        ulonglong2 Y4 = *(const ulonglong2*)&sY[s];
        ulonglong2 Z4 = *(const ulonglong2*)&sZ[s];
        u64 dA2 = fma2(aE2, E4.x, fma2(ax2, X4.x, fma2(ay2, Y4.x, mul2(az2, Z4.x))));
        u64 dB2 = fma2(aE2, E4.y, fma2(ax2, X4.y, fma2(ay2, Y4.y, mul2(az2, Z4.y))));
        float2 dA = unpack2(dA2);
        float2 dB = unpack2(dB2);
        if (fmaxf(fmaxf(dA.x, dA.y), fmaxf(dB.x, dB.y)) >= th) {
            CAPTURE(dA.x, s);
            CAPTURE(dA.y, s + 1);
            CAPTURE(dB.x, s + 2);
            CAPTURE(dB.y, s + 3);
        }
    }
    for (int s = s1; s < q1; s++) {
        float d = fmaf(aE, sE[s], fmaf(ax, sX[s], fmaf(ay, sY[s], az * sZ[s])));
        CAPTURE(d, s);
    }

    // ---- build quarter list: stable-desc-sort(A) ++ ties(B asc index) ----
    float v[8]; int idA[8]; int bReg[8];
#pragma unroll
    for (int j = 0; j < 8; j++) {
        v[j]   = (j < na) ? av[j] : -FLT_MAX;
        idA[j] = (j < na) ? ai[j] : 0;
        bReg[j] = bi[j];
    }
#pragma unroll
    for (int i = 0; i < 7; i++) {
#pragma unroll
        for (int j = 0; j < 7 - i; j++) {
            bool p = v[j + 1] > v[j];   // strict -> stable
            float hv = p ? v[j + 1] : v[j];
            float lv = p ? v[j] : v[j + 1];
            int hi_ = p ? idA[j + 1] : idA[j];
            int lo_ = p ? idA[j] : idA[j + 1];
            v[j] = hv; v[j + 1] = lv; idA[j] = hi_; idA[j + 1] = lo_;
        }
    }
    // write final quarter list (desc) into sAv/sAi (reuse)
#pragma unroll
    for (int j = 0; j < 8; j++) {
        int jb = j - na; jb = jb < 0 ? 0 : (jb > 7 ? 7 : jb);
        av[j] = (j < na) ? v[j] : th;
        ai[j] = (j < na) ? idA[j] : bReg[jb];
    }
    __syncthreads();

    // ---- warp 0: 4-way merge + cumsum ----
    if (w == 0) {
        int gt = (b * T_ + t) * 3;
        if (t >= len) {
            g_mass[gt + 0] = mv; g_mass[gt + 1] = mv; g_mass[gt + 2] = mv;
        } else {
            int p0 = 0, p1 = 0, p2 = 0, p3 = 0;
            float v0 = sAv[(0 * 32 + lane) * 8];
            float v1 = sAv[(1 * 32 + lane) * 8];
            float v2 = sAv[(2 * 32 + lane) * 8];
            float v3 = sAv[(3 * 32 + lane) * 8];
            float cE = 0.f, cX = 0.f, cY = 0.f, cZ = 0.f;
            float m[3]; int kk = 0;
#pragma unroll
            for (int j = 0; j < 8; j++) {
                float bv = v3; int bq = 3;
                if (v2 >= bv) { bv = v2; bq = 2; }
                if (v1 >= bv) { bv = v1; bq = 1; }
                if (v0 >= bv) { bv = v0; bq = 0; }
                int ix;
                if (bq == 0) { ix = sAi[(0 * 32 + lane) * 8 + p0]; p0++; v0 = (p0 < 8) ? sAv[(0 * 32 + lane) * 8 + p0] : -FLT_MAX; }
                else if (bq == 1) { ix = sAi[(1 * 32 + lane) * 8 + p1]; p1++; v1 = (p1 < 8) ? sAv[(1 * 32 + lane) * 8 + p1] : -FLT_MAX; }
                else if (bq == 2) { ix = sAi[(2 * 32 + lane) * 8 + p2]; p2++; v2 = (p2 < 8) ? sAv[(2 * 32 + lane) * 8 + p2] : -FLT_MAX; }
                else { ix = sAi[(3 * 32 + lane) * 8 + p3]; p3++; v3 = (p3 < 8) ? sAv[(3 * 32 + lane) * 8 + p3] : -FLT_MAX; }
                cE += sE[ix]; cX += sX[ix]; cY += sY[ix]; cZ += sZ[ix];
                if (j == 1 || j == 3 || j == 7) {
                    float m2 = fmaf(cE, cE, -fmaf(cX, cX, fmaf(cY, cY, cZ * cZ)));
                    m[kk++] = sqrtf(fmaxf(m2, 0.f) + 1e-8f);
                }
            }
            g_mass[gt + 0] = m[0]; g_mass[gt + 1] = m[1]; g_mass[gt + 2] = m[2];
        }
    }
}

// =========================================================================
// Kernel 3: MLP  out = gelu(mass@W1 + b1) @ W2 + b2
// Block = 128 tokens x 128 cols (one col-quarter). h[64] in registers,
// W2 quarter broadcast from smem, stores staged through smem for coalescing.
// =========================================================================
__global__ __launch_bounds__(128) void mlp_kernel(
    const float* __restrict__ W1, const float* __restrict__ b1,
    const float* __restrict__ W2, const float* __restrict__ b2,
    float* __restrict__ out)
{
    __shared__ __align__(16) float sW2[H_ * 128];   // 32 KB: W2[:, quarter]
    __shared__ __align__(16) float sStage[128 * 20];// 10 KB: staging (pad 20)
    __shared__ __align__(16) float sW1[3 * H_];
    __shared__ __align__(16) float sb1[H_];
    __shared__ __align__(16) float sb2[128];
    __shared__ __align__(16) float sMrow[128];

    int tid = threadIdx.x;
    int quarter = blockIdx.x & 3;
    int tok0 = (blockIdx.x >> 2) * 128;
    int qbase = quarter * 128;

    for (int i = tid; i < 3 * H_; i += 128) sW1[i] = W1[i];   // FIX: 192 > 128
    if (tid < H_) sb1[tid] = b1[tid];
    sb2[tid] = b2[qbase + tid];
    sMrow[tid] = g_mrow[qbase + tid];
#pragma unroll
    for (int i = 0; i < 16; i++) {              // 2048 float4 / 128 threads
        int idx = i * 128 + tid;
        int row = idx >> 5, c4 = idx & 31;
        *(float4*)&sW2[row * 128 + c4 * 4] =
            *(const float4*)&W2[row * D_ + qbase + c4 * 4];
    }
    __syncthreads();

    int tt = tok0 + tid;
    int b = tt >> 11;
    bool masked = (tt & (T_ - 1)) >= g_len[b];
    bool allm = __all_sync(0xffffffffu, masked);

    float h[H_];
    if (!allm) {
        float m0 = g_mass[tt * 3 + 0];
        float m1 = g_mass[tt * 3 + 1];
        float m2v = g_mass[tt * 3 + 2];
#pragma unroll
        for (int j = 0; j < H_; j++) {
            float x = fmaf(m0, sW1[j], fmaf(m1, sW1[H_ + j], fmaf(m2v, sW1[2 * H_ + j], sb1[j])));
            h[j] = gelu(x);
        }
    }

    for (int ch = 0; ch < 8; ch++) {            // 8 chunks of 16 cols
        if (!allm) {
            u64 acc[8];
#pragma unroll
            for (int c = 0; c < 8; c++)
                acc[c] = pack2(sb2[ch * 16 + 2 * c], sb2[ch * 16 + 2 * c + 1]);
#pragma unroll
            for (int k = 0; k < H_; k++) {
                u64 hd = dup2(h[k]);
                const ulonglong2* wr = (const ulonglong2*)&sW2[k * 128 + ch * 16];
                ulonglong2 w0 = wr[0], w1 = wr[1], w2 = wr[2], w3 = wr[3];
                acc[0] = fma2(hd, w0.x, acc[0]);
                acc[1] = fma2(hd, w0.y, acc[1]);
                acc[2] = fma2(hd, w1.x, acc[2]);
                acc[3] = fma2(hd, w1.y, acc[3]);
                acc[4] = fma2(hd, w2.x, acc[4]);
                acc[5] = fma2(hd, w2.y, acc[5]);
                acc[6] = fma2(hd, w3.x, acc[6]);
                acc[7] = fma2(hd, w3.y, acc[7]);
            }
#pragma unroll
            for (int c = 0; c < 8; c++) {
                float2 f = unpack2(acc[c]);
                *(float2*)&sStage[tid * 20 + 2 * c] = f;
            }
        } else {
#pragma unroll
            for (int c = 0; c < 8; c++) {
                float lo = sMrow[ch * 16 + 2 * c];
                float hi = sMrow[ch * 16 + 2 * c + 1];
                *(float2*)&sStage[tid * 20 + 2 * c] = make_float2(lo, hi);
            }
        }
        __syncthreads();
        // coalesced store: 128 tokens x 16 cols = 512 float4
#pragma unroll
        for (int i = 0; i < 4; i++) {
            int idx = i * 128 + tid;
            int tr = idx >> 2, c4 = idx & 3;
            float4 val = *(const float4*)&sStage[tr * 20 + c4 * 4];
            *(float4*)&out[(size_t)(tok0 + tr) * D_ + qbase + ch * 16 + c4 * 4] = val;
        }
        __syncthreads();
    }
}

// =========================================================================
extern "C" void kernel_launch(void* const* d_in, const int* in_sizes, int n_in,
                              void* d_out, int out_size)
{
    const float* tokens        = (const float*)d_in[0];
    const unsigned char* mask  = (const unsigned char*)d_in[1];
    const float* W1            = (const float*)d_in[2];
    const float* b1            = (const float*)d_in[3];
    const float* W2            = (const float*)d_in[4];
    const float* b2            = (const float*)d_in[5];
    float* out                 = (float*)d_out;

    len_kernel<<<B_, 256>>>(mask);
    prep_kernel<<<(B_ * T_) / 256, 256>>>(tokens);
    mrow_kernel<<<1, 512>>>(W1, b1, W2, b2);
    mass_kernel<<<dim3(T_ / 32, B_), 128>>>();
    mlp_kernel<<<(B_ * T_ / 128) * 4, 128>>>(W1, b1, W2, b2, out);
}

// round 6
// speedup vs baseline: 1.1421x; 1.0278x over previous
#include <cuda_runtime.h>
#include <math.h>
#include <stdint.h>
#include <float.h>

#define B_ 16
#define T_ 2048
#define D_ 512
#define H_ 64

typedef unsigned long long u64;

// ---------------- device scratch (no allocations allowed) ----------------
__device__ float4 g_P[B_ * T_];          // 4-momenta
__device__ int    g_len[B_];             // valid lengths per batch
__device__ float  g_mass[B_ * T_ * 3];   // masses for k=2,4,8
__device__ float  g_mrow[D_];            // output row for masked tokens

// ---------------- f32x2 packed helpers ----------------
__device__ __forceinline__ u64 dup2(float a) {
    u64 r; asm("mov.b64 %0, {%1, %1};" : "=l"(r) : "f"(a)); return r;
}
__device__ __forceinline__ u64 pack2(float lo, float hi) {
    u64 r; asm("mov.b64 %0, {%1, %2};" : "=l"(r) : "f"(lo), "f"(hi)); return r;
}
__device__ __forceinline__ float2 unpack2(u64 v) {
    float2 f; asm("mov.b64 {%0, %1}, %2;" : "=f"(f.x), "=f"(f.y) : "l"(v)); return f;
}
__device__ __forceinline__ u64 fma2(u64 a, u64 b, u64 c) {
    u64 d; asm("fma.rn.f32x2 %0, %1, %2, %3;" : "=l"(d) : "l"(a), "l"(b), "l"(c)); return d;
}
__device__ __forceinline__ u64 mul2(u64 a, u64 b) {
    u64 d; asm("mul.rn.f32x2 %0, %1, %2;" : "=l"(d) : "l"(a), "l"(b)); return d;
}
__device__ __forceinline__ float gelu(float x) {
    return 0.5f * x * (1.f + erff(x * 0.70710678118654752f));
}

// =========================================================================
// Kernel 0: per-batch valid length (mask dtype detected at runtime).
// =========================================================================
__global__ __launch_bounds__(256) void len_kernel(const unsigned char* __restrict__ mask)
{
    int b = blockIdx.x;
    unsigned int w0 = *(const unsigned int*)mask;
    bool byteMode = (w0 == 0x01010101u);

    int cnt = 0;
    for (int s = threadIdx.x; s < T_; s += 256) {
        unsigned int mv = byteMode ? (unsigned int)mask[b * T_ + s]
                                   : ((const unsigned int*)mask)[b * T_ + s];
        cnt += (mv != 0u);
    }
    for (int o = 16; o; o >>= 1) cnt += __shfl_down_sync(0xffffffffu, cnt, o);
    __shared__ int sred[8];
    if ((threadIdx.x & 31) == 0) sred[threadIdx.x >> 5] = cnt;
    __syncthreads();
    if (threadIdx.x == 0) {
        int tot = 0;
#pragma unroll
        for (int i = 0; i < 8; i++) tot += sred[i];
        g_len[b] = tot;
    }
}

// =========================================================================
// Kernel 1: 4-momenta.
// =========================================================================
__global__ __launch_bounds__(256) void prep_kernel(const float* __restrict__ tokens)
{
    int gt = blockIdx.x * 256 + threadIdx.x;
    float4 tk = ((const float4*)tokens)[gt];
    float E = tk.x, Pt = tk.y, eta = tk.z, phi = tk.w;
    eta = fminf(fmaxf(eta, -20.f), 20.f);
    float sp, cp;
    sincosf(phi, &sp, &cp);
    g_P[gt] = make_float4(E, Pt * cp, Pt * sp, Pt * sinhf(eta));
}

// =========================================================================
// Kernel 1b: output row for masked tokens (all masses == sqrt(1e-8)).
// =========================================================================
__global__ __launch_bounds__(512) void mrow_kernel(
    const float* __restrict__ W1, const float* __restrict__ b1,
    const float* __restrict__ W2, const float* __restrict__ b2)
{
    __shared__ float hm[H_];
    int tid = threadIdx.x;
    float mv = sqrtf(1e-8f);
    if (tid < H_) {
        float x = fmaf(mv, W1[tid], fmaf(mv, W1[H_ + tid], fmaf(mv, W1[2 * H_ + tid], b1[tid])));
        hm[tid] = gelu(x);
    }
    __syncthreads();
    float acc = b2[tid];
#pragma unroll 16
    for (int k = 0; k < H_; k++) acc = fmaf(hm[k], W2[k * D_ + tid], acc);
    g_mrow[tid] = acc;
}

// =========================================================================
// Kernel 2: per-token top-8 Minkowski dot -> masses (k=2,4,8).
// Block = 32 tokens (lane <-> token), 8 warps each scan an EIGHTH of
// [0,len). Per eighth: pass1 value-only FMNMX top-8 (8 elems/iter for ILP),
// pass2 tie-exact A/B capture. Warp 0 8-way-merges (value desc, eighth asc
// on ties == global index asc) and does the cumsum -> masses.
// Dynamic smem (56 KB > 48 KB static limit).
// =========================================================================
#define VINS(dv) do { float c = (dv), t_;                 \
    t_ = fminf(c, th1); c = fmaxf(c, th1); th0 = t_;      \
    t_ = fminf(c, th2); c = fmaxf(c, th2); th1 = t_;      \
    t_ = fminf(c, th3); c = fmaxf(c, th3); th2 = t_;      \
    t_ = fminf(c, th4); c = fmaxf(c, th4); th3 = t_;      \
    t_ = fminf(c, th5); c = fmaxf(c, th5); th4 = t_;      \
    t_ = fminf(c, th6); c = fmaxf(c, th6); th5 = t_;      \
    t_ = fminf(c, th7); c = fmaxf(c, th7); th6 = t_;      \
    th7 = c;                                              \
} while (0)

#define CAPTURE(dv, si) do {                                          \
    float _d = (dv);                                                  \
    if (_d >= th) {                                                   \
        if (_d > th) {                                                \
            if (na < 8) { av[na] = _d; ai[na] = (si); na++; }         \
        } else {                                                      \
            if (nb < 8) { bi[nb] = (si); nb++; }                      \
        }                                                             \
    }                                                                 \
} while (0)

// dot of 8 consecutive elements starting at s (16B-aligned)
#define DOT8()                                                                     \
    ulonglong2 E01 = *(const ulonglong2*)&sE[s];                                   \
    ulonglong2 E23 = *(const ulonglong2*)&sE[s + 4];                               \
    ulonglong2 X01 = *(const ulonglong2*)&sX[s];                                   \
    ulonglong2 X23 = *(const ulonglong2*)&sX[s + 4];                               \
    ulonglong2 Y01 = *(const ulonglong2*)&sY[s];                                   \
    ulonglong2 Y23 = *(const ulonglong2*)&sY[s + 4];                               \
    ulonglong2 Z01 = *(const ulonglong2*)&sZ[s];                                   \
    ulonglong2 Z23 = *(const ulonglong2*)&sZ[s + 4];                               \
    u64 p0 = fma2(aE2, E01.x, fma2(ax2, X01.x, fma2(ay2, Y01.x, mul2(az2, Z01.x))));\
    u64 p1 = fma2(aE2, E01.y, fma2(ax2, X01.y, fma2(ay2, Y01.y, mul2(az2, Z01.y))));\
    u64 p2 = fma2(aE2, E23.x, fma2(ax2, X23.x, fma2(ay2, Y23.x, mul2(az2, Z23.x))));\
    u64 p3 = fma2(aE2, E23.y, fma2(ax2, X23.y, fma2(ay2, Y23.y, mul2(az2, Z23.y))));\
    float2 d0 = unpack2(p0), d1 = unpack2(p1), d2 = unpack2(p2), d3 = unpack2(p3); \
    float gmax = fmaxf(fmaxf(fmaxf(d0.x, d0.y), fmaxf(d1.x, d1.y)),                \
                       fmaxf(fmaxf(d2.x, d2.y), fmaxf(d3.x, d3.y)));

__global__ __launch_bounds__(256) void mass_kernel()
{
    extern __shared__ __align__(16) unsigned char smem_raw[];
    float* sE  = (float*)smem_raw;            // [2048]
    float* sX  = sE + T_;                     // [2048]
    float* sY  = sX + T_;                     // [2048]
    float* sZ  = sY + T_;                     // [2048]
    float* sAv = sZ + T_;                     // [256*8]
    int*   sAi = (int*)(sAv + 256 * 8);       // [256*8]
    int*   sBi = sAi + 256 * 8;               // [256*8]

    int b = blockIdx.y;
    int len = g_len[b];
    int tbase = blockIdx.x * 32;
    int tid = threadIdx.x, lane = tid & 31, w = tid >> 5;
    float mv = sqrtf(1e-8f);

    if (tbase >= len) {                 // whole block masked
        if (tid < 96) g_mass[(b * T_ + tbase) * 3 + tid] = mv;
        return;
    }

    const float4* gp = g_P + b * T_;
    for (int i = tid; i < T_; i += 256) {
        float4 p = gp[i];
        sE[i] = p.x; sX[i] = p.y; sY[i] = p.z; sZ[i] = p.w;
    }
    __syncthreads();

    int t = tbase + lane;
    int q0 = (w * len) >> 3;
    int q1 = ((w + 1) * len) >> 3;

    float aE = sE[t], ax = -sX[t], ay = -sY[t], az = -sZ[t];  // metric folded
    u64 aE2 = dup2(aE), ax2 = dup2(ax), ay2 = dup2(ay), az2 = dup2(az);

    float th0 = -FLT_MAX, th1 = -FLT_MAX, th2 = -FLT_MAX, th3 = -FLT_MAX;
    float th4 = -FLT_MAX, th5 = -FLT_MAX, th6 = -FLT_MAX, th7 = -FLT_MAX;

    // identical region split for both passes (threshold exactness requires it)
    int s0 = (q0 + 3) & ~3; if (s0 > q1) s0 = q1;        // 16B-aligned start
    int s1 = s0 + ((q1 - s0) & ~7);                       // 8-elem main region

    // ---- pass 1: eighth-local top-8 values ----
    for (int s = q0; s < s0; s++) {
        float d = fmaf(aE, sE[s], fmaf(ax, sX[s], fmaf(ay, sY[s], az * sZ[s])));
        if (d > th0) VINS(d);
    }
    for (int s = s0; s < s1; s += 8) {
        DOT8();
        if (gmax > th0) {
            if (d0.x > th0) VINS(d0.x);
            if (d0.y > th0) VINS(d0.y);
            if (d1.x > th0) VINS(d1.x);
            if (d1.y > th0) VINS(d1.y);
            if (d2.x > th0) VINS(d2.x);
            if (d2.y > th0) VINS(d2.y);
            if (d3.x > th0) VINS(d3.x);
            if (d3.y > th0) VINS(d3.y);
        }
    }
    for (int s = s1; s < q1; s++) {
        float d = fmaf(aE, sE[s], fmaf(ax, sX[s], fmaf(ay, sY[s], az * sZ[s])));
        if (d > th0) VINS(d);
    }

    // ---- pass 2: tie-exact index capture in ascending s ----
    float th = th0;
    float* av = &sAv[tid * 8];
    int*   ai = &sAi[tid * 8];
    int*   bi = &sBi[tid * 8];
    int na = 0, nb = 0;

    for (int s = q0; s < s0; s++) {
        float d = fmaf(aE, sE[s], fmaf(ax, sX[s], fmaf(ay, sY[s], az * sZ[s])));
        CAPTURE(d, s);
    }
    for (int s = s0; s < s1; s += 8) {
        DOT8();
        if (gmax >= th) {
            CAPTURE(d0.x, s);
            CAPTURE(d0.y, s + 1);
            CAPTURE(d1.x, s + 2);
            CAPTURE(d1.y, s + 3);
            CAPTURE(d2.x, s + 4);
            CAPTURE(d2.y, s + 5);
            CAPTURE(d3.x, s + 6);
            CAPTURE(d3.y, s + 7);
        }
    }
    for (int s = s1; s < q1; s++) {
        float d = fmaf(aE, sE[s], fmaf(ax, sX[s], fmaf(ay, sY[s], az * sZ[s])));
        CAPTURE(d, s);
    }

    // ---- build eighth list: stable-desc-sort(A) ++ ties(B asc index) ----
    {
        float v[8]; int idA[8]; int bReg[8];
#pragma unroll
        for (int j = 0; j < 8; j++) {
            v[j]   = (j < na) ? av[j] : -FLT_MAX;
            idA[j] = (j < na) ? ai[j] : 0;
            bReg[j] = bi[j];
        }
#pragma unroll
        for (int i = 0; i < 7; i++) {
#pragma unroll
            for (int j = 0; j < 7 - i; j++) {
                bool p = v[j + 1] > v[j];   // strict -> stable
                float hv = p ? v[j + 1] : v[j];
                float lv = p ? v[j] : v[j + 1];
                int hi_ = p ? idA[j + 1] : idA[j];
                int lo_ = p ? idA[j] : idA[j + 1];
                v[j] = hv; v[j + 1] = lv; idA[j] = hi_; idA[j + 1] = lo_;
            }
        }
#pragma unroll
        for (int j = 0; j < 8; j++) {
            int jb = j - na; jb = jb < 0 ? 0 : (jb > 7 ? 7 : jb);
            av[j] = (j < na) ? v[j] : th;
            ai[j] = (j < na) ? idA[j] : bReg[jb];
        }
    }
    __syncthreads();

    // ---- warp 0: 8-way merge + cumsum ----
    if (w == 0) {
        int gt3 = (b * T_ + t) * 3;
        if (t >= len) {
            g_mass[gt3 + 0] = mv; g_mass[gt3 + 1] = mv; g_mass[gt3 + 2] = mv;
        } else {
            float vh[8]; int pp[8];
#pragma unroll
            for (int q = 0; q < 8; q++) {
                pp[q] = 0;
                vh[q] = sAv[(q * 32 + lane) * 8];
            }
            float cE = 0.f, cX = 0.f, cY = 0.f, cZ = 0.f;
            float m[3]; int kk = 0;
#pragma unroll
            for (int j = 0; j < 8; j++) {
                int bq = 0; float bv = vh[0];
#pragma unroll
                for (int q = 1; q < 8; q++)
                    if (vh[q] > bv) { bv = vh[q]; bq = q; }   // strict: tie -> lower eighth
                int ix = 0;
#pragma unroll
                for (int q = 0; q < 8; q++) {
                    if (bq == q) {
                        ix = sAi[(q * 32 + lane) * 8 + pp[q]];
                        pp[q]++;
                        vh[q] = (pp[q] < 8) ? sAv[(q * 32 + lane) * 8 + pp[q]] : -FLT_MAX;
                    }
                }
                cE += sE[ix]; cX += sX[ix]; cY += sY[ix]; cZ += sZ[ix];
                if (j == 1 || j == 3 || j == 7) {
                    float m2 = fmaf(cE, cE, -fmaf(cX, cX, fmaf(cY, cY, cZ * cZ)));
                    m[kk++] = sqrtf(fmaxf(m2, 0.f) + 1e-8f);
                }
            }
            g_mass[gt3 + 0] = m[0]; g_mass[gt3 + 1] = m[1]; g_mass[gt3 + 2] = m[2];
        }
    }
}

// =========================================================================
// Kernel 3: MLP  out = gelu(mass@W1 + b1) @ W2 + b2   (unchanged from R5)
// =========================================================================
__global__ __launch_bounds__(128) void mlp_kernel(
    const float* __restrict__ W1, const float* __restrict__ b1,
    const float* __restrict__ W2, const float* __restrict__ b2,
    float* __restrict__ out)
{
    __shared__ __align__(16) float sW2[H_ * 128];   // 32 KB: W2[:, quarter]
    __shared__ __align__(16) float sStage[128 * 20];// 10 KB: staging (pad 20)
    __shared__ __align__(16) float sW1[3 * H_];
    __shared__ __align__(16) float sb1[H_];
    __shared__ __align__(16) float sb2[128];
    __shared__ __align__(16) float sMrow[128];

    int tid = threadIdx.x;
    int quarter = blockIdx.x & 3;
    int tok0 = (blockIdx.x >> 2) * 128;
    int qbase = quarter * 128;

    for (int i = tid; i < 3 * H_; i += 128) sW1[i] = W1[i];
    if (tid < H_) sb1[tid] = b1[tid];
    sb2[tid] = b2[qbase + tid];
    sMrow[tid] = g_mrow[qbase + tid];
#pragma unroll
    for (int i = 0; i < 16; i++) {              // 2048 float4 / 128 threads
        int idx = i * 128 + tid;
        int row = idx >> 5, c4 = idx & 31;
        *(float4*)&sW2[row * 128 + c4 * 4] =
            *(const float4*)&W2[row * D_ + qbase + c4 * 4];
    }
    __syncthreads();

    int tt = tok0 + tid;
    int b = tt >> 11;
    bool masked = (tt & (T_ - 1)) >= g_len[b];
    bool allm = __all_sync(0xffffffffu, masked);

    float h[H_];
    if (!allm) {
        float m0 = g_mass[tt * 3 + 0];
        float m1 = g_mass[tt * 3 + 1];
        float m2v = g_mass[tt * 3 + 2];
#pragma unroll
        for (int j = 0; j < H_; j++) {
            float x = fmaf(m0, sW1[j], fmaf(m1, sW1[H_ + j], fmaf(m2v, sW1[2 * H_ + j], sb1[j])));
            h[j] = gelu(x);
        }
    }

    for (int ch = 0; ch < 8; ch++) {            // 8 chunks of 16 cols
        if (!allm) {
            u64 acc[8];
#pragma unroll
            for (int c = 0; c < 8; c++)
                acc[c] = pack2(sb2[ch * 16 + 2 * c], sb2[ch * 16 + 2 * c + 1]);
#pragma unroll
            for (int k = 0; k < H_; k++) {
                u64 hd = dup2(h[k]);
                const ulonglong2* wr = (const ulonglong2*)&sW2[k * 128 + ch * 16];
                ulonglong2 w0 = wr[0], w1 = wr[1], w2 = wr[2], w3 = wr[3];
                acc[0] = fma2(hd, w0.x, acc[0]);
                acc[1] = fma2(hd, w0.y, acc[1]);
                acc[2] = fma2(hd, w1.x, acc[2]);
                acc[3] = fma2(hd, w1.y, acc[3]);
                acc[4] = fma2(hd, w2.x, acc[4]);
                acc[5] = fma2(hd, w2.y, acc[5]);
                acc[6] = fma2(hd, w3.x, acc[6]);
                acc[7] = fma2(hd, w3.y, acc[7]);
            }
#pragma unroll
            for (int c = 0; c < 8; c++) {
                float2 f = unpack2(acc[c]);
                *(float2*)&sStage[tid * 20 + 2 * c] = f;
            }
        } else {
#pragma unroll
            for (int c = 0; c < 8; c++) {
                float lo = sMrow[ch * 16 + 2 * c];
                float hi = sMrow[ch * 16 + 2 * c + 1];
                *(float2*)&sStage[tid * 20 + 2 * c] = make_float2(lo, hi);
            }
        }
        __syncthreads();
#pragma unroll
        for (int i = 0; i < 4; i++) {
            int idx = i * 128 + tid;
            int tr = idx >> 2, c4 = idx & 3;
            float4 val = *(const float4*)&sStage[tr * 20 + c4 * 4];
            *(float4*)&out[(size_t)(tok0 + tr) * D_ + qbase + ch * 16 + c4 * 4] = val;
        }
        __syncthreads();
    }
}

// =========================================================================
extern "C" void kernel_launch(void* const* d_in, const int* in_sizes, int n_in,
                              void* d_out, int out_size)
{
    const float* tokens        = (const float*)d_in[0];
    const unsigned char* mask  = (const unsigned char*)d_in[1];
    const float* W1            = (const float*)d_in[2];
    const float* b1            = (const float*)d_in[3];
    const float* W2            = (const float*)d_in[4];
    const float* b2            = (const float*)d_in[5];
    float* out                 = (float*)d_out;

    const int massSmem = (4 * T_ + 3 * 256 * 8) * 4;   // 57344 bytes
    cudaFuncSetAttribute(mass_kernel,
                         cudaFuncAttributeMaxDynamicSharedMemorySize, massSmem);

    len_kernel<<<B_, 256>>>(mask);
    prep_kernel<<<(B_ * T_) / 256, 256>>>(tokens);
    mrow_kernel<<<1, 512>>>(W1, b1, W2, b2);
    mass_kernel<<<dim3(T_ / 32, B_), 256, massSmem>>>();
    mlp_kernel<<<(B_ * T_ / 128) * 4, 128>>>(W1, b1, W2, b2, out);
}

// round 8
// speedup vs baseline: 1.2479x; 1.0926x over previous
#include <cuda_runtime.h>
#include <cuda_bf16.h>
#include <math.h>
#include <stdint.h>
#include <float.h>

#define B_ 16
#define T_ 2048
#define D_ 512
#define H_ 64

typedef unsigned long long u64;

// ---------------- device scratch (no allocations allowed) ----------------
__device__ float4 g_P[B_ * T_];                    // 4-momenta
__device__ int    g_len[B_];                       // valid lengths per batch
__device__ float  g_mass[B_ * T_ * 3];             // masses for k=2,4,8
__device__ __nv_bfloat16 g_Ahi[B_ * T_ * H_];      // h split hi
__device__ __nv_bfloat16 g_Alo[B_ * T_ * H_];      // h split lo
__device__ __nv_bfloat16 g_Bhi[D_ * H_];           // W2^T split hi  [n][k]
__device__ __nv_bfloat16 g_Blo[D_ * H_];           // W2^T split lo  [n][k]

// ---------------- f32x2 packed helpers ----------------
__device__ __forceinline__ u64 dup2(float a) {
    u64 r; asm("mov.b64 %0, {%1, %1};" : "=l"(r) : "f"(a)); return r;
}
__device__ __forceinline__ float2 unpack2(u64 v) {
    float2 f; asm("mov.b64 {%0, %1}, %2;" : "=f"(f.x), "=f"(f.y) : "l"(v)); return f;
}
__device__ __forceinline__ u64 fma2(u64 a, u64 b, u64 c) {
    u64 d; asm("fma.rn.f32x2 %0, %1, %2, %3;" : "=l"(d) : "l"(a), "l"(b), "l"(c)); return d;
}
__device__ __forceinline__ u64 mul2(u64 a, u64 b) {
    u64 d; asm("mul.rn.f32x2 %0, %1, %2;" : "=l"(d) : "l"(a), "l"(b)); return d;
}
__device__ __forceinline__ float gelu(float x) {
    return 0.5f * x * (1.f + erff(x * 0.70710678118654752f));
}

// bf16 mma m16n8k16, f32 accum (plain PTX, works on sm_103 non-'a' target)
#define MMA16816(d, a, b) \
    asm volatile("mma.sync.aligned.m16n8k16.row.col.f32.bf16.bf16.f32 " \
        "{%0,%1,%2,%3}, {%4,%5,%6,%7}, {%8,%9}, {%0,%1,%2,%3};" \
        : "+f"((d)[0]), "+f"((d)[1]), "+f"((d)[2]), "+f"((d)[3]) \
        : "r"((a)[0]), "r"((a)[1]), "r"((a)[2]), "r"((a)[3]), \
          "r"((b)[0]), "r"((b)[1]))

// =========================================================================
// Kernel 0: per-batch valid length (mask dtype detected at runtime).
// =========================================================================
__global__ __launch_bounds__(256) void len_kernel(const unsigned char* __restrict__ mask)
{
    int b = blockIdx.x;
    unsigned int w0 = *(const unsigned int*)mask;
    bool byteMode = (w0 == 0x01010101u);

    int cnt = 0;
    for (int s = threadIdx.x; s < T_; s += 256) {
        unsigned int mv = byteMode ? (unsigned int)mask[b * T_ + s]
                                   : ((const unsigned int*)mask)[b * T_ + s];
        cnt += (mv != 0u);
    }
    for (int o = 16; o; o >>= 1) cnt += __shfl_down_sync(0xffffffffu, cnt, o);
    __shared__ int sred[8];
    if ((threadIdx.x & 31) == 0) sred[threadIdx.x >> 5] = cnt;
    __syncthreads();
    if (threadIdx.x == 0) {
        int tot = 0;
#pragma unroll
        for (int i = 0; i < 8; i++) tot += sred[i];
        g_len[b] = tot;
    }
}

// =========================================================================
// Kernel 1: 4-momenta.
// =========================================================================
__global__ __launch_bounds__(256) void prep_kernel(const float* __restrict__ tokens)
{
    int gt = blockIdx.x * 256 + threadIdx.x;
    float4 tk = ((const float4*)tokens)[gt];
    float E = tk.x, Pt = tk.y, eta = tk.z, phi = tk.w;
    eta = fminf(fmaxf(eta, -20.f), 20.f);
    float sp, cp;
    sincosf(phi, &sp, &cp);
    g_P[gt] = make_float4(E, Pt * cp, Pt * sp, Pt * sinhf(eta));
}

// =========================================================================
// Kernel 1c: W2^T bf16 hi/lo planes.  g_B*[n*64+k] = split(W2[k*512+n])
// =========================================================================
__global__ __launch_bounds__(256) void w2t_kernel(const float* __restrict__ W2)
{
    int idx = blockIdx.x * 256 + threadIdx.x;   // 0..32767
    int k = idx >> 9;          // 0..63
    int n = idx & 511;         // coalesced read of W2 row k
    float wv = W2[k * D_ + n];
    __nv_bfloat16 h = __float2bfloat16(wv);
    g_Bhi[n * H_ + k] = h;
    g_Blo[n * H_ + k] = __float2bfloat16(wv - __bfloat162float(h));
}

// =========================================================================
// Kernel 2: per-token top-8 Minkowski dot -> masses (k=2,4,8).
// Block = 32 tokens (lane<->token), 8 warps scan eighths.
// Pass 1: branch-free bitonic top-8 (sort8 group + half-cleaner merge).
// Pass 2: tie-exact A/B capture vs th0. Warp 0 8-way merge + cumsum.
// =========================================================================
#define CEA(a, b) do { float _l = fminf(a, b), _h = fmaxf(a, b); (a) = _l; (b) = _h; } while (0)

// ascending value-only single insert (tails); th0 = min .. th7 = max
#define VINS(dv) do { float c = (dv), t_;                 \
    t_ = fminf(c, th1); c = fmaxf(c, th1); th0 = t_;      \
    t_ = fminf(c, th2); c = fmaxf(c, th2); th1 = t_;      \
    t_ = fminf(c, th3); c = fmaxf(c, th3); th2 = t_;      \
    t_ = fminf(c, th4); c = fmaxf(c, th4); th3 = t_;      \
    t_ = fminf(c, th5); c = fmaxf(c, th5); th4 = t_;      \
    t_ = fminf(c, th6); c = fmaxf(c, th6); th5 = t_;      \
    t_ = fminf(c, th7); c = fmaxf(c, th7); th6 = t_;      \
    th7 = c;                                              \
} while (0)

#define CAPTURE(dv, si) do {                                          \
    float _d = (dv);                                                  \
    if (_d >= th) {                                                   \
        if (_d > th) {                                                \
            if (na < 8) { av[na] = _d; ai[na] = (si); na++; }         \
        } else {                                                      \
            if (nb < 8) { bi[nb] = (si); nb++; }                      \
        }                                                             \
    }                                                                 \
} while (0)

#define DOT8()                                                                     \
    ulonglong2 E01 = *(const ulonglong2*)&sE[s];                                   \
    ulonglong2 E23 = *(const ulonglong2*)&sE[s + 4];                               \
    ulonglong2 X01 = *(const ulonglong2*)&sX[s];                                   \
    ulonglong2 X23 = *(const ulonglong2*)&sX[s + 4];                               \
    ulonglong2 Y01 = *(const ulonglong2*)&sY[s];                                   \
    ulonglong2 Y23 = *(const ulonglong2*)&sY[s + 4];                               \
    ulonglong2 Z01 = *(const ulonglong2*)&sZ[s];                                   \
    ulonglong2 Z23 = *(const ulonglong2*)&sZ[s + 4];                               \
    u64 p0 = fma2(aE2, E01.x, fma2(ax2, X01.x, fma2(ay2, Y01.x, mul2(az2, Z01.x))));\
    u64 p1 = fma2(aE2, E01.y, fma2(ax2, X01.y, fma2(ay2, Y01.y, mul2(az2, Z01.y))));\
    u64 p2 = fma2(aE2, E23.x, fma2(ax2, X23.x, fma2(ay2, Y23.x, mul2(az2, Z23.x))));\
    u64 p3 = fma2(aE2, E23.y, fma2(ax2, X23.y, fma2(ay2, Y23.y, mul2(az2, Z23.y))));\
    float2 d0 = unpack2(p0), d1 = unpack2(p1), d2 = unpack2(p2), d3 = unpack2(p3); \
    float gmax = fmaxf(fmaxf(fmaxf(d0.x, d0.y), fmaxf(d1.x, d1.y)),                \
                       fmaxf(fmaxf(d2.x, d2.y), fmaxf(d3.x, d3.y)));

__global__ __launch_bounds__(256) void mass_kernel()
{
    extern __shared__ __align__(16) unsigned char smem_raw[];
    float* sE  = (float*)smem_raw;
    float* sX  = sE + T_;
    float* sY  = sX + T_;
    float* sZ  = sY + T_;
    float* sAv = sZ + T_;
    int*   sAi = (int*)(sAv + 256 * 8);
    int*   sBi = sAi + 256 * 8;

    int b = blockIdx.y;
    int len = g_len[b];
    int tbase = blockIdx.x * 32;
    int tid = threadIdx.x, lane = tid & 31, w = tid >> 5;
    float mv = sqrtf(1e-8f);

    if (tbase >= len) {
        if (tid < 96) g_mass[(b * T_ + tbase) * 3 + tid] = mv;
        return;
    }

    const float4* gp = g_P + b * T_;
    for (int i = tid; i < T_; i += 256) {
        float4 p = gp[i];
        sE[i] = p.x; sX[i] = p.y; sY[i] = p.z; sZ[i] = p.w;
    }
    __syncthreads();

    int t = tbase + lane;
    int q0 = (w * len) >> 3;
    int q1 = ((w + 1) * len) >> 3;

    float aE = sE[t], ax = -sX[t], ay = -sY[t], az = -sZ[t];
    u64 aE2 = dup2(aE), ax2 = dup2(ax), ay2 = dup2(ay), az2 = dup2(az);

    float th0 = -FLT_MAX, th1 = -FLT_MAX, th2 = -FLT_MAX, th3 = -FLT_MAX;
    float th4 = -FLT_MAX, th5 = -FLT_MAX, th6 = -FLT_MAX, th7 = -FLT_MAX;

    int s0 = (q0 + 3) & ~3; if (s0 > q1) s0 = q1;
    int s1 = s0 + ((q1 - s0) & ~7);

    // ---- pass 1: top-8 values (branch-free bitonic group merge) ----
    for (int s = q0; s < s0; s++) {
        float d = fmaf(aE, sE[s], fmaf(ax, sX[s], fmaf(ay, sY[s], az * sZ[s])));
        if (d > th0) VINS(d);
    }
    for (int s = s0; s < s1; s += 8) {
        DOT8();
        if (gmax > th0) {
            float v0 = d0.x, v1 = d0.y, v2 = d1.x, v3 = d1.y;
            float v4 = d2.x, v5 = d2.y, v6 = d3.x, v7 = d3.y;
            // Batcher odd-even mergesort-8 (ascending), 19 CEs
            CEA(v0, v1); CEA(v2, v3); CEA(v4, v5); CEA(v6, v7);
            CEA(v0, v2); CEA(v1, v3); CEA(v4, v6); CEA(v5, v7);
            CEA(v1, v2); CEA(v5, v6);
            CEA(v0, v4); CEA(v1, v5); CEA(v2, v6); CEA(v3, v7);
            CEA(v2, v4); CEA(v3, v5);
            CEA(v1, v2); CEA(v3, v4); CEA(v5, v6);
            // half-cleaner: top-8 multiset of union (t asc, v asc)
            float m0 = fmaxf(th0, v7), m1 = fmaxf(th1, v6);
            float m2 = fmaxf(th2, v5), m3 = fmaxf(th3, v4);
            float m4 = fmaxf(th4, v3), m5 = fmaxf(th5, v2);
            float m6 = fmaxf(th6, v1), m7 = fmaxf(th7, v0);
            // bitonic clean (asc), 12 CEs
            CEA(m0, m4); CEA(m1, m5); CEA(m2, m6); CEA(m3, m7);
            CEA(m0, m2); CEA(m1, m3); CEA(m4, m6); CEA(m5, m7);
            CEA(m0, m1); CEA(m2, m3); CEA(m4, m5); CEA(m6, m7);
            th0 = m0; th1 = m1; th2 = m2; th3 = m3;
            th4 = m4; th5 = m5; th6 = m6; th7 = m7;
        }
    }
    for (int s = s1; s < q1; s++) {
        float d = fmaf(aE, sE[s], fmaf(ax, sX[s], fmaf(ay, sY[s], az * sZ[s])));
        if (d > th0) VINS(d);
    }

    // ---- pass 2: tie-exact index capture in ascending s ----
    float th = th0;
    float* av = &sAv[tid * 8];
    int*   ai = &sAi[tid * 8];
    int*   bi = &sBi[tid * 8];
    int na = 0, nb = 0;

    for (int s = q0; s < s0; s++) {
        float d = fmaf(aE, sE[s], fmaf(ax, sX[s], fmaf(ay, sY[s], az * sZ[s])));
        CAPTURE(d, s);
    }
    for (int s = s0; s < s1; s += 8) {
        DOT8();
        if (gmax >= th) {
            CAPTURE(d0.x, s);
            CAPTURE(d0.y, s + 1);
            CAPTURE(d1.x, s + 2);
            CAPTURE(d1.y, s + 3);
            CAPTURE(d2.x, s + 4);
            CAPTURE(d2.y, s + 5);
            CAPTURE(d3.x, s + 6);
            CAPTURE(d3.y, s + 7);
        }
    }
    for (int s = s1; s < q1; s++) {
        float d = fmaf(aE, sE[s], fmaf(ax, sX[s], fmaf(ay, sY[s], az * sZ[s])));
        CAPTURE(d, s);
    }

    // ---- build eighth list: stable-desc-sort(A) ++ ties(B asc index) ----
    {
        float v[8]; int idA[8]; int bReg[8];
#pragma unroll
        for (int j = 0; j < 8; j++) {
            v[j]   = (j < na) ? av[j] : -FLT_MAX;
            idA[j] = (j < na) ? ai[j] : 0;
            bReg[j] = bi[j];
        }
#pragma unroll
        for (int i = 0; i < 7; i++) {
#pragma unroll
            for (int j = 0; j < 7 - i; j++) {
                bool p = v[j + 1] > v[j];
                float hv = p ? v[j + 1] : v[j];
                float lv = p ? v[j] : v[j + 1];
                int hi_ = p ? idA[j + 1] : idA[j];
                int lo_ = p ? idA[j] : idA[j + 1];
                v[j] = hv; v[j + 1] = lv; idA[j] = hi_; idA[j + 1] = lo_;
            }
        }
#pragma unroll
        for (int j = 0; j < 8; j++) {
            int jb = j - na; jb = jb < 0 ? 0 : (jb > 7 ? 7 : jb);
            av[j] = (j < na) ? v[j] : th;
            ai[j] = (j < na) ? idA[j] : bReg[jb];
        }
    }
    __syncthreads();

    // ---- warp 0: 8-way merge + cumsum ----
    if (w == 0) {
        int gt3 = (b * T_ + t) * 3;
        if (t >= len) {
            g_mass[gt3 + 0] = mv; g_mass[gt3 + 1] = mv; g_mass[gt3 + 2] = mv;
        } else {
            float vh[8]; int pp[8];
#pragma unroll
            for (int q = 0; q < 8; q++) { pp[q] = 0; vh[q] = sAv[(q * 32 + lane) * 8]; }
            float cE = 0.f, cX = 0.f, cY = 0.f, cZ = 0.f;
            float m[3]; int kk = 0;
#pragma unroll
            for (int j = 0; j < 8; j++) {
                int bq = 0; float bv = vh[0];
#pragma unroll
                for (int q = 1; q < 8; q++)
                    if (vh[q] > bv) { bv = vh[q]; bq = q; }   // tie -> lower eighth
                int ix = 0;
#pragma unroll
                for (int q = 0; q < 8; q++) {
                    if (bq == q) {
                        ix = sAi[(q * 32 + lane) * 8 + pp[q]];
                        pp[q]++;
                        vh[q] = (pp[q] < 8) ? sAv[(q * 32 + lane) * 8 + pp[q]] : -FLT_MAX;
                    }
                }
                cE += sE[ix]; cX += sX[ix]; cY += sY[ix]; cZ += sZ[ix];
                if (j == 1 || j == 3 || j == 7) {
                    float m2 = fmaf(cE, cE, -fmaf(cX, cX, fmaf(cY, cY, cZ * cZ)));
                    m[kk++] = sqrtf(fmaxf(m2, 0.f) + 1e-8f);
                }
            }
            g_mass[gt3 + 0] = m[0]; g_mass[gt3 + 1] = m[1]; g_mass[gt3 + 2] = m[2];
        }
    }
}

// =========================================================================
// Kernel 3a: h = gelu(mass@W1 + b1), split into bf16 hi/lo planes.
// =========================================================================
__global__ __launch_bounds__(256) void h_kernel(
    const float* __restrict__ W1, const float* __restrict__ b1)
{
    __shared__ float sW1[3 * H_];
    __shared__ float sb1[H_];
    int tid = threadIdx.x;
    if (tid < 3 * H_) sW1[tid] = W1[tid];
    if (tid < H_) sb1[tid] = b1[tid];
    __syncthreads();

    int t = blockIdx.x * 256 + tid;
    float m0 = g_mass[t * 3 + 0];
    float m1 = g_mass[t * 3 + 1];
    float m2 = g_mass[t * 3 + 2];

#pragma unroll
    for (int jb = 0; jb < 8; jb++) {
        __align__(16) __nv_bfloat16 hi8[8];
        __align__(16) __nv_bfloat16 lo8[8];
#pragma unroll
        for (int j = 0; j < 8; j++) {
            int k = jb * 8 + j;
            float x = fmaf(m0, sW1[k], fmaf(m1, sW1[H_ + k], fmaf(m2, sW1[2 * H_ + k], sb1[k])));
            float g = gelu(x);
            __nv_bfloat16 h = __float2bfloat16(g);
            hi8[j] = h;
            lo8[j] = __float2bfloat16(g - __bfloat162float(h));
        }
        *(uint4*)&g_Ahi[(size_t)t * H_ + jb * 8] = *(const uint4*)hi8;
        *(uint4*)&g_Alo[(size_t)t * H_ + jb * 8] = *(const uint4*)lo8;
    }
}

// =========================================================================
// Kernel 3b: out = h @ W2 + b2 via mma.sync m16n8k16 bf16 (split, 3 terms).
// Block = 4 warps; tile M=64 tokens x N=128 cols; warp = 64x32, K=64.
// =========================================================================
__global__ __launch_bounds__(128) void mlp_mma(
    const float* __restrict__ b2, float* __restrict__ out)
{
    int tid = threadIdx.x, lane = tid & 31, w = tid >> 5;
    int cb = (blockIdx.x & 3) * 128;
    int tok0 = (blockIdx.x >> 2) * 64;
    int n0 = cb + w * 32;
    int grp = lane >> 2;        // 0..7
    int qid = lane & 3;         // 0..3

    float acc[4][4][4];
#pragma unroll
    for (int nt = 0; nt < 4; nt++) {
        float2 bb = *(const float2*)&b2[n0 + nt * 8 + qid * 2];
#pragma unroll
        for (int mt = 0; mt < 4; mt++) {
            acc[mt][nt][0] = bb.x; acc[mt][nt][1] = bb.y;
            acc[mt][nt][2] = bb.x; acc[mt][nt][3] = bb.y;
        }
    }

    const __nv_bfloat16* Ah = g_Ahi + (size_t)tok0 * H_;
    const __nv_bfloat16* Al = g_Alo + (size_t)tok0 * H_;

#pragma unroll
    for (int ks = 0; ks < 4; ks++) {
        int k0 = ks * 16 + qid * 2;
        uint32_t ah[4][4], al[4][4];
#pragma unroll
        for (int mt = 0; mt < 4; mt++) {
            int r0 = mt * 16 + grp;
            ah[mt][0] = *(const uint32_t*)&Ah[r0 * H_ + k0];
            ah[mt][1] = *(const uint32_t*)&Ah[(r0 + 8) * H_ + k0];
            ah[mt][2] = *(const uint32_t*)&Ah[r0 * H_ + k0 + 8];
            ah[mt][3] = *(const uint32_t*)&Ah[(r0 + 8) * H_ + k0 + 8];
            al[mt][0] = *(const uint32_t*)&Al[r0 * H_ + k0];
            al[mt][1] = *(const uint32_t*)&Al[(r0 + 8) * H_ + k0];
            al[mt][2] = *(const uint32_t*)&Al[r0 * H_ + k0 + 8];
            al[mt][3] = *(const uint32_t*)&Al[(r0 + 8) * H_ + k0 + 8];
        }
        uint32_t bh[4][2], bl[4][2];
#pragma unroll
        for (int nt = 0; nt < 4; nt++) {
            int n = n0 + nt * 8 + grp;
            bh[nt][0] = *(const uint32_t*)&g_Bhi[n * H_ + k0];
            bh[nt][1] = *(const uint32_t*)&g_Bhi[n * H_ + k0 + 8];
            bl[nt][0] = *(const uint32_t*)&g_Blo[n * H_ + k0];
            bl[nt][1] = *(const uint32_t*)&g_Blo[n * H_ + k0 + 8];
        }
#pragma unroll
        for (int mt = 0; mt < 4; mt++) {
#pragma unroll
            for (int nt = 0; nt < 4; nt++) {
                MMA16816(acc[mt][nt], ah[mt], bh[nt]);
                MMA16816(acc[mt][nt], ah[mt], bl[nt]);
                MMA16816(acc[mt][nt], al[mt], bh[nt]);
            }
        }
    }

    // store: d0,d1 -> (row, col..col+1); d2,d3 -> (row+8, ...)
#pragma unroll
    for (int mt = 0; mt < 4; mt++) {
        int row = tok0 + mt * 16 + grp;
#pragma unroll
        for (int nt = 0; nt < 4; nt++) {
            int c = n0 + nt * 8 + qid * 2;
            *(float2*)&out[(size_t)row * D_ + c] =
                make_float2(acc[mt][nt][0], acc[mt][nt][1]);
            *(float2*)&out[(size_t)(row + 8) * D_ + c] =
                make_float2(acc[mt][nt][2], acc[mt][nt][3]);
        }
    }
}

// =========================================================================
extern "C" void kernel_launch(void* const* d_in, const int* in_sizes, int n_in,
                              void* d_out, int out_size)
{
    const float* tokens        = (const float*)d_in[0];
    const unsigned char* mask  = (const unsigned char*)d_in[1];
    const float* W1            = (const float*)d_in[2];
    const float* b1            = (const float*)d_in[3];
    const float* W2            = (const float*)d_in[4];
    const float* b2            = (const float*)d_in[5];
    float* out                 = (float*)d_out;

    const int massSmem = (4 * T_ + 3 * 256 * 8) * 4;   // 57344 bytes
    cudaFuncSetAttribute(mass_kernel,
                         cudaFuncAttributeMaxDynamicSharedMemorySize, massSmem);

    len_kernel<<<B_, 256>>>(mask);
    prep_kernel<<<(B_ * T_) / 256, 256>>>(tokens);
    w2t_kernel<<<(D_ * H_) / 256, 256>>>(W2);
    mass_kernel<<<dim3(T_ / 32, B_), 256, massSmem>>>();
    h_kernel<<<(B_ * T_) / 256, 256>>>(W1, b1);
    mlp_mma<<<(B_ * T_ / 64) * 4, 128>>>(b2, out);
}

// round 9
// speedup vs baseline: 1.5675x; 1.2561x over previous
#include <cuda_runtime.h>
#include <cuda_bf16.h>
#include <math.h>
#include <stdint.h>
#include <float.h>

#define B_ 16
#define T_ 2048
#define D_ 512
#define H_ 64

typedef unsigned long long u64;

// ---------------- device scratch (no allocations allowed) ----------------
__device__ float4 g_P[B_ * T_];                    // 4-momenta
__device__ int    g_len[B_];                       // valid lengths per batch
__device__ float  g_mass[B_ * T_ * 3];             // masses for k=2,4,8
__device__ __nv_bfloat16 g_Ahi[B_ * T_ * H_];      // h split hi
__device__ __nv_bfloat16 g_Alo[B_ * T_ * H_];      // h split lo
__device__ __nv_bfloat16 g_Bhi[D_ * H_];           // W2^T split hi  [n][k]
__device__ __nv_bfloat16 g_Blo[D_ * H_];           // W2^T split lo  [n][k]

// ---------------- f32x2 packed helpers ----------------
__device__ __forceinline__ u64 dup2(float a) {
    u64 r; asm("mov.b64 %0, {%1, %1};" : "=l"(r) : "f"(a)); return r;
}
__device__ __forceinline__ float2 unpack2(u64 v) {
    float2 f; asm("mov.b64 {%0, %1}, %2;" : "=f"(f.x), "=f"(f.y) : "l"(v)); return f;
}
__device__ __forceinline__ u64 fma2(u64 a, u64 b, u64 c) {
    u64 d; asm("fma.rn.f32x2 %0, %1, %2, %3;" : "=l"(d) : "l"(a), "l"(b), "l"(c)); return d;
}
__device__ __forceinline__ u64 mul2(u64 a, u64 b) {
    u64 d; asm("mul.rn.f32x2 %0, %1, %2;" : "=l"(d) : "l"(a), "l"(b)); return d;
}
__device__ __forceinline__ float gelu(float x) {
    return 0.5f * x * (1.f + erff(x * 0.70710678118654752f));
}
__device__ __forceinline__ uint32_t smem_u32(const void* p) {
    uint32_t a;
    asm("{ .reg .u64 t; cvta.to.shared.u64 t, %1; cvt.u32.u64 %0, t; }"
        : "=r"(a) : "l"(p));
    return a;
}

// bf16 mma m16n8k16, f32 accum (plain PTX, sm_80+, OK on sm_103 target)
#define MMA16816(d, a, b) \
    asm volatile("mma.sync.aligned.m16n8k16.row.col.f32.bf16.bf16.f32 " \
        "{%0,%1,%2,%3}, {%4,%5,%6,%7}, {%8,%9}, {%0,%1,%2,%3};" \
        : "+f"((d)[0]), "+f"((d)[1]), "+f"((d)[2]), "+f"((d)[3]) \
        : "r"((a)[0]), "r"((a)[1]), "r"((a)[2]), "r"((a)[3]), \
          "r"((b)[0]), "r"((b)[1]))

__device__ __forceinline__ void ldm_x4(uint32_t* r, uint32_t saddr) {
    asm volatile("ldmatrix.sync.aligned.m8n8.x4.shared.b16 {%0,%1,%2,%3}, [%4];"
        : "=r"(r[0]), "=r"(r[1]), "=r"(r[2]), "=r"(r[3]) : "r"(saddr));
}

#define SWZ(o) ((o) ^ (((o) >> 3) & 0x70))

// =========================================================================
// Kernel 0: per-batch valid length (mask dtype detected at runtime).
// =========================================================================
__global__ __launch_bounds__(256) void len_kernel(const unsigned char* __restrict__ mask)
{
    int b = blockIdx.x;
    unsigned int w0 = *(const unsigned int*)mask;
    bool byteMode = (w0 == 0x01010101u);

    int cnt = 0;
    for (int s = threadIdx.x; s < T_; s += 256) {
        unsigned int mv = byteMode ? (unsigned int)mask[b * T_ + s]
                                   : ((const unsigned int*)mask)[b * T_ + s];
        cnt += (mv != 0u);
    }
    for (int o = 16; o; o >>= 1) cnt += __shfl_down_sync(0xffffffffu, cnt, o);
    __shared__ int sred[8];
    if ((threadIdx.x & 31) == 0) sred[threadIdx.x >> 5] = cnt;
    __syncthreads();
    if (threadIdx.x == 0) {
        int tot = 0;
#pragma unroll
        for (int i = 0; i < 8; i++) tot += sred[i];
        g_len[b] = tot;
    }
}

// =========================================================================
// Kernel 1: 4-momenta.
// =========================================================================
__global__ __launch_bounds__(256) void prep_kernel(const float* __restrict__ tokens)
{
    int gt = blockIdx.x * 256 + threadIdx.x;
    float4 tk = ((const float4*)tokens)[gt];
    float E = tk.x, Pt = tk.y, eta = tk.z, phi = tk.w;
    eta = fminf(fmaxf(eta, -20.f), 20.f);
    float sp, cp;
    sincosf(phi, &sp, &cp);
    g_P[gt] = make_float4(E, Pt * cp, Pt * sp, Pt * sinhf(eta));
}

// =========================================================================
// Kernel 1c: W2^T bf16 hi/lo planes.  g_B*[n*64+k] = split(W2[k*512+n])
// =========================================================================
__global__ __launch_bounds__(256) void w2t_kernel(const float* __restrict__ W2)
{
    int idx = blockIdx.x * 256 + threadIdx.x;   // 0..32767
    int k = idx >> 9;
    int n = idx & 511;
    float wv = W2[k * D_ + n];
    __nv_bfloat16 h = __float2bfloat16(wv);
    g_Bhi[n * H_ + k] = h;
    g_Blo[n * H_ + k] = __float2bfloat16(wv - __bfloat162float(h));
}

// =========================================================================
// Kernel 2: per-token top-8 Minkowski dot -> masses (k=2,4,8).
// Pass 1: 16-elem batched branch-free top-8 (2x sort8 + half-cleaners).
// Pass 2: tie-exact A/B capture vs th0. Warp 0 8-way merge + cumsum.
// =========================================================================
#define CEA(a, b) do { float _l = fminf(a, b), _h = fmaxf(a, b); (a) = _l; (b) = _h; } while (0)

#define SORT8A(v0,v1,v2,v3,v4,v5,v6,v7) do {                 \
    CEA(v0, v1); CEA(v2, v3); CEA(v4, v5); CEA(v6, v7);      \
    CEA(v0, v2); CEA(v1, v3); CEA(v4, v6); CEA(v5, v7);      \
    CEA(v1, v2); CEA(v5, v6);                                \
    CEA(v0, v4); CEA(v1, v5); CEA(v2, v6); CEA(v3, v7);      \
    CEA(v2, v4); CEA(v3, v5);                                \
    CEA(v1, v2); CEA(v3, v4); CEA(v5, v6);                   \
} while (0)

#define CLEAN8(m0,m1,m2,m3,m4,m5,m6,m7) do {                 \
    CEA(m0, m4); CEA(m1, m5); CEA(m2, m6); CEA(m3, m7);      \
    CEA(m0, m2); CEA(m1, m3); CEA(m4, m6); CEA(m5, m7);      \
    CEA(m0, m1); CEA(m2, m3); CEA(m4, m5); CEA(m6, m7);      \
} while (0)

// ascending value-only single insert (tails); th0 = min .. th7 = max
#define VINS(dv) do { float c = (dv), t_;                 \
    t_ = fminf(c, th1); c = fmaxf(c, th1); th0 = t_;      \
    t_ = fminf(c, th2); c = fmaxf(c, th2); th1 = t_;      \
    t_ = fminf(c, th3); c = fmaxf(c, th3); th2 = t_;      \
    t_ = fminf(c, th4); c = fmaxf(c, th4); th3 = t_;      \
    t_ = fminf(c, th5); c = fmaxf(c, th5); th4 = t_;      \
    t_ = fminf(c, th6); c = fmaxf(c, th6); th5 = t_;      \
    t_ = fminf(c, th7); c = fmaxf(c, th7); th6 = t_;      \
    th7 = c;                                              \
} while (0)

#define CAPTURE(dv, si) do {                                          \
    float _d = (dv);                                                  \
    if (_d >= th) {                                                   \
        if (_d > th) {                                                \
            if (na < 8) { av[na] = _d; ai[na] = (si); na++; }         \
        } else {                                                      \
            if (nb < 8) { bi[nb] = (si); nb++; }                      \
        }                                                             \
    }                                                                 \
} while (0)

__device__ __forceinline__ void dot8f(
    const float* sE, const float* sX, const float* sY, const float* sZ,
    int s, u64 aE2, u64 ax2, u64 ay2, u64 az2, float* v)
{
    ulonglong2 E01 = *(const ulonglong2*)&sE[s];
    ulonglong2 X01 = *(const ulonglong2*)&sX[s];
    ulonglong2 Y01 = *(const ulonglong2*)&sY[s];
    ulonglong2 Z01 = *(const ulonglong2*)&sZ[s];
    u64 p0 = fma2(aE2, E01.x, fma2(ax2, X01.x, fma2(ay2, Y01.x, mul2(az2, Z01.x))));
    u64 p1 = fma2(aE2, E01.y, fma2(ax2, X01.y, fma2(ay2, Y01.y, mul2(az2, Z01.y))));
    float2 d0 = unpack2(p0), d1 = unpack2(p1);
    v[0] = d0.x; v[1] = d0.y; v[2] = d1.x; v[3] = d1.y;
}

__global__ __launch_bounds__(256) void mass_kernel()
{
    extern __shared__ __align__(16) unsigned char smem_raw[];
    float* sE  = (float*)smem_raw;
    float* sX  = sE + T_;
    float* sY  = sX + T_;
    float* sZ  = sY + T_;
    float* sAv = sZ + T_;
    int*   sAi = (int*)(sAv + 256 * 8);
    int*   sBi = sAi + 256 * 8;

    int b = blockIdx.y;
    int len = g_len[b];
    int tbase = blockIdx.x * 32;
    int tid = threadIdx.x, lane = tid & 31, w = tid >> 5;
    float mv = sqrtf(1e-8f);

    if (tbase >= len) {
        if (tid < 96) g_mass[(b * T_ + tbase) * 3 + tid] = mv;
        return;
    }

    const float4* gp = g_P + b * T_;
    for (int i = tid; i < T_; i += 256) {
        float4 p = gp[i];
        sE[i] = p.x; sX[i] = p.y; sY[i] = p.z; sZ[i] = p.w;
    }
    __syncthreads();

    int t = tbase + lane;
    int q0 = (w * len) >> 3;
    int q1 = ((w + 1) * len) >> 3;

    float aE = sE[t], ax = -sX[t], ay = -sY[t], az = -sZ[t];
    u64 aE2 = dup2(aE), ax2 = dup2(ax), ay2 = dup2(ay), az2 = dup2(az);

    float th0 = -FLT_MAX, th1 = -FLT_MAX, th2 = -FLT_MAX, th3 = -FLT_MAX;
    float th4 = -FLT_MAX, th5 = -FLT_MAX, th6 = -FLT_MAX, th7 = -FLT_MAX;

    int s0 = (q0 + 3) & ~3; if (s0 > q1) s0 = q1;
    int s1a = s0 + ((q1 - s0) & ~15);     // pass-1 main (16-elem batches)
    int s1b = s0 + ((q1 - s0) & ~7);      // pass-2 main (8-elem batches)

    // ---- pass 1: always-sort batched top-8 (value-multiset exact) ----
    for (int s = q0; s < s0; s++) {
        float d = fmaf(aE, sE[s], fmaf(ax, sX[s], fmaf(ay, sY[s], az * sZ[s])));
        if (d > th0) VINS(d);
    }
    for (int s = s0; s < s1a; s += 16) {
        float v[16];
        dot8f(sE, sX, sY, sZ, s,      aE2, ax2, ay2, az2, v);
        dot8f(sE, sX, sY, sZ, s + 4,  aE2, ax2, ay2, az2, v + 4);
        dot8f(sE, sX, sY, sZ, s + 8,  aE2, ax2, ay2, az2, v + 8);
        dot8f(sE, sX, sY, sZ, s + 12, aE2, ax2, ay2, az2, v + 12);
        SORT8A(v[0], v[1], v[2], v[3], v[4], v[5], v[6], v[7]);
        SORT8A(v[8], v[9], v[10], v[11], v[12], v[13], v[14], v[15]);
        // top-8 of the 16 (half-cleaner) -> bitonic -> clean
        float m0 = fmaxf(v[0], v[15]), m1 = fmaxf(v[1], v[14]);
        float m2 = fmaxf(v[2], v[13]), m3 = fmaxf(v[3], v[12]);
        float m4 = fmaxf(v[4], v[11]), m5 = fmaxf(v[5], v[10]);
        float m6 = fmaxf(v[6], v[9]),  m7 = fmaxf(v[7], v[8]);
        CLEAN8(m0, m1, m2, m3, m4, m5, m6, m7);
        // merge with running top-8 (both asc)
        float u0 = fmaxf(th0, m7), u1 = fmaxf(th1, m6);
        float u2 = fmaxf(th2, m5), u3 = fmaxf(th3, m4);
        float u4 = fmaxf(th4, m3), u5 = fmaxf(th5, m2);
        float u6 = fmaxf(th6, m1), u7 = fmaxf(th7, m0);
        CLEAN8(u0, u1, u2, u3, u4, u5, u6, u7);
        th0 = u0; th1 = u1; th2 = u2; th3 = u3;
        th4 = u4; th5 = u5; th6 = u6; th7 = u7;
    }
    for (int s = s1a; s < q1; s++) {
        float d = fmaf(aE, sE[s], fmaf(ax, sX[s], fmaf(ay, sY[s], az * sZ[s])));
        if (d > th0) VINS(d);
    }

    // ---- pass 2: tie-exact index capture in ascending s ----
    float th = th0;
    float* av = &sAv[tid * 8];
    int*   ai = &sAi[tid * 8];
    int*   bi = &sBi[tid * 8];
    int na = 0, nb = 0;

    for (int s = q0; s < s0; s++) {
        float d = fmaf(aE, sE[s], fmaf(ax, sX[s], fmaf(ay, sY[s], az * sZ[s])));
        CAPTURE(d, s);
    }
    for (int s = s0; s < s1b; s += 8) {
        float v[8];
        dot8f(sE, sX, sY, sZ, s,     aE2, ax2, ay2, az2, v);
        dot8f(sE, sX, sY, sZ, s + 4, aE2, ax2, ay2, az2, v + 4);
        float gmax = fmaxf(fmaxf(fmaxf(v[0], v[1]), fmaxf(v[2], v[3])),
                           fmaxf(fmaxf(v[4], v[5]), fmaxf(v[6], v[7])));
        if (gmax >= th) {
            CAPTURE(v[0], s);
            CAPTURE(v[1], s + 1);
            CAPTURE(v[2], s + 2);
            CAPTURE(v[3], s + 3);
            CAPTURE(v[4], s + 4);
            CAPTURE(v[5], s + 5);
            CAPTURE(v[6], s + 6);
            CAPTURE(v[7], s + 7);
        }
    }
    for (int s = s1b; s < q1; s++) {
        float d = fmaf(aE, sE[s], fmaf(ax, sX[s], fmaf(ay, sY[s], az * sZ[s])));
        CAPTURE(d, s);
    }

    // ---- build eighth list: stable-desc-sort(A) ++ ties(B asc index) ----
    {
        float v[8]; int idA[8]; int bReg[8];
#pragma unroll
        for (int j = 0; j < 8; j++) {
            v[j]   = (j < na) ? av[j] : -FLT_MAX;
            idA[j] = (j < na) ? ai[j] : 0;
            bReg[j] = bi[j];
        }
#pragma unroll
        for (int i = 0; i < 7; i++) {
#pragma unroll
            for (int j = 0; j < 7 - i; j++) {
                bool p = v[j + 1] > v[j];
                float hv = p ? v[j + 1] : v[j];
                float lv = p ? v[j] : v[j + 1];
                int hi_ = p ? idA[j + 1] : idA[j];
                int lo_ = p ? idA[j] : idA[j + 1];
                v[j] = hv; v[j + 1] = lv; idA[j] = hi_; idA[j + 1] = lo_;
            }
        }
#pragma unroll
        for (int j = 0; j < 8; j++) {
            int jb = j - na; jb = jb < 0 ? 0 : (jb > 7 ? 7 : jb);
            av[j] = (j < na) ? v[j] : th;
            ai[j] = (j < na) ? idA[j] : bReg[jb];
        }
    }
    __syncthreads();

    // ---- warp 0: 8-way merge + cumsum ----
    if (w == 0) {
        int gt3 = (b * T_ + t) * 3;
        if (t >= len) {
            g_mass[gt3 + 0] = mv; g_mass[gt3 + 1] = mv; g_mass[gt3 + 2] = mv;
        } else {
            float vh[8]; int pp[8];
#pragma unroll
            for (int q = 0; q < 8; q++) { pp[q] = 0; vh[q] = sAv[(q * 32 + lane) * 8]; }
            float cE = 0.f, cX = 0.f, cY = 0.f, cZ = 0.f;
            float m[3]; int kk = 0;
#pragma unroll
            for (int j = 0; j < 8; j++) {
                int bq = 0; float bv = vh[0];
#pragma unroll
                for (int q = 1; q < 8; q++)
                    if (vh[q] > bv) { bv = vh[q]; bq = q; }   // tie -> lower eighth
                int ix = 0;
#pragma unroll
                for (int q = 0; q < 8; q++) {
                    if (bq == q) {
                        ix = sAi[(q * 32 + lane) * 8 + pp[q]];
                        pp[q]++;
                        vh[q] = (pp[q] < 8) ? sAv[(q * 32 + lane) * 8 + pp[q]] : -FLT_MAX;
                    }
                }
                cE += sE[ix]; cX += sX[ix]; cY += sY[ix]; cZ += sZ[ix];
                if (j == 1 || j == 3 || j == 7) {
                    float m2 = fmaf(cE, cE, -fmaf(cX, cX, fmaf(cY, cY, cZ * cZ)));
                    m[kk++] = sqrtf(fmaxf(m2, 0.f) + 1e-8f);
                }
            }
            g_mass[gt3 + 0] = m[0]; g_mass[gt3 + 1] = m[1]; g_mass[gt3 + 2] = m[2];
        }
    }
}

// =========================================================================
// Kernel 3a: h = gelu(mass@W1 + b1), split into bf16 hi/lo planes.
// =========================================================================
__global__ __launch_bounds__(256) void h_kernel(
    const float* __restrict__ W1, const float* __restrict__ b1)
{
    __shared__ float sW1[3 * H_];
    __shared__ float sb1[H_];
    int tid = threadIdx.x;
    if (tid < 3 * H_) sW1[tid] = W1[tid];
    if (tid < H_) sb1[tid] = b1[tid];
    __syncthreads();

    int t = blockIdx.x * 256 + tid;
    float m0 = g_mass[t * 3 + 0];
    float m1 = g_mass[t * 3 + 1];
    float m2 = g_mass[t * 3 + 2];

#pragma unroll
    for (int jb = 0; jb < 8; jb++) {
        __align__(16) __nv_bfloat16 hi8[8];
        __align__(16) __nv_bfloat16 lo8[8];
#pragma unroll
        for (int j = 0; j < 8; j++) {
            int k = jb * 8 + j;
            float x = fmaf(m0, sW1[k], fmaf(m1, sW1[H_ + k], fmaf(m2, sW1[2 * H_ + k], sb1[k])));
            float g = gelu(x);
            __nv_bfloat16 h = __float2bfloat16(g);
            hi8[j] = h;
            lo8[j] = __float2bfloat16(g - __bfloat162float(h));
        }
        *(uint4*)&g_Ahi[(size_t)t * H_ + jb * 8] = *(const uint4*)hi8;
        *(uint4*)&g_Alo[(size_t)t * H_ + jb * 8] = *(const uint4*)lo8;
    }
}

// =========================================================================
// Kernel 3b: out = h @ W2 + b2 via mma.sync (split bf16, 3 terms).
// Block = 256 thr (8 warps): 128 tokens x 128 cols; warp = 32 tok x 64 col.
// Tiles staged in smem (SW128) and fed via ldmatrix.
// =========================================================================
__global__ __launch_bounds__(256) void mlp_mma(
    const float* __restrict__ b2, float* __restrict__ out)
{
    extern __shared__ __align__(1024) unsigned char sm[];
    unsigned char* sAhi = sm;
    unsigned char* sAlo = sm + 16384;
    unsigned char* sBhi = sm + 32768;
    unsigned char* sBlo = sm + 49152;

    int tid = threadIdx.x, lane = tid & 31, w = tid >> 5;
    int cb = (blockIdx.x & 3) * 128;
    int tok0 = (blockIdx.x >> 2) * 128;
    int wm = w & 3, wn = w >> 2;
    int qid = lane & 3, grp = lane >> 2;
    int rl = lane & 15, cl = lane >> 4;

    // ---- stage tiles (coalesced uint4, swizzled store) ----
#pragma unroll
    for (int i = 0; i < 4; i++) {
        int idx = i * 256 + tid;           // 0..1023
        int row = idx >> 3, c = idx & 7;
        uint32_t o = SWZ((uint32_t)(row * 128 + c * 16));
        *(uint4*)(sAhi + o) = ((const uint4*)(g_Ahi + (size_t)(tok0 + row) * H_))[c];
        *(uint4*)(sAlo + o) = ((const uint4*)(g_Alo + (size_t)(tok0 + row) * H_))[c];
        *(uint4*)(sBhi + o) = ((const uint4*)(g_Bhi + (size_t)(cb + row) * H_))[c];
        *(uint4*)(sBlo + o) = ((const uint4*)(g_Blo + (size_t)(cb + row) * H_))[c];
    }
    __syncthreads();

    uint32_t aAhi = smem_u32(sAhi), aAlo = smem_u32(sAlo);
    uint32_t aBhi = smem_u32(sBhi), aBlo = smem_u32(sBlo);

    // ---- init acc with b2 ----
    float acc[2][8][4];
#pragma unroll
    for (int nt = 0; nt < 8; nt++) {
        float2 bb = *(const float2*)&b2[cb + wn * 64 + nt * 8 + qid * 2];
#pragma unroll
        for (int mt = 0; mt < 2; mt++) {
            acc[mt][nt][0] = bb.x; acc[mt][nt][1] = bb.y;
            acc[mt][nt][2] = bb.x; acc[mt][nt][3] = bb.y;
        }
    }

    // ---- main loop over K (4 x k16) ----
#pragma unroll
    for (int ks = 0; ks < 4; ks++) {
        uint32_t ah[2][4], al[2][4];
#pragma unroll
        for (int mt = 0; mt < 2; mt++) {
            uint32_t o = SWZ((uint32_t)((wm * 32 + mt * 16 + rl) * 128 + (ks * 2 + cl) * 16));
            ldm_x4(ah[mt], aAhi + o);
            ldm_x4(al[mt], aAlo + o);
        }
#pragma unroll
        for (int ntp = 0; ntp < 4; ntp++) {
            uint32_t bh[4], bl[4];
            uint32_t ob = SWZ((uint32_t)((wn * 64 + ntp * 16 + rl) * 128 + (ks * 2 + cl) * 16));
            ldm_x4(bh, aBhi + ob);
            ldm_x4(bl, aBlo + ob);
            uint32_t bfh0[2] = {bh[0], bh[2]}, bfh1[2] = {bh[1], bh[3]};
            uint32_t bfl0[2] = {bl[0], bl[2]}, bfl1[2] = {bl[1], bl[3]};
#pragma unroll
            for (int mt = 0; mt < 2; mt++) {
                MMA16816(acc[mt][ntp * 2],     ah[mt], bfh0);
                MMA16816(acc[mt][ntp * 2],     ah[mt], bfl0);
                MMA16816(acc[mt][ntp * 2],     al[mt], bfh0);
                MMA16816(acc[mt][ntp * 2 + 1], ah[mt], bfh1);
                MMA16816(acc[mt][ntp * 2 + 1], ah[mt], bfl1);
                MMA16816(acc[mt][ntp * 2 + 1], al[mt], bfh1);
            }
        }
    }

    // ---- store ----
#pragma unroll
    for (int mt = 0; mt < 2; mt++) {
        int row = tok0 + wm * 32 + mt * 16 + grp;
#pragma unroll
        for (int nt = 0; nt < 8; nt++) {
            int c = cb + wn * 64 + nt * 8 + qid * 2;
            *(float2*)&out[(size_t)row * D_ + c] =
                make_float2(acc[mt][nt][0], acc[mt][nt][1]);
            *(float2*)&out[(size_t)(row + 8) * D_ + c] =
                make_float2(acc[mt][nt][2], acc[mt][nt][3]);
        }
    }
}

// =========================================================================
extern "C" void kernel_launch(void* const* d_in, const int* in_sizes, int n_in,
                              void* d_out, int out_size)
{
    const float* tokens        = (const float*)d_in[0];
    const unsigned char* mask  = (const unsigned char*)d_in[1];
    const float* W1            = (const float*)d_in[2];
    const float* b1            = (const float*)d_in[3];
    const float* W2            = (const float*)d_in[4];
    const float* b2            = (const float*)d_in[5];
    float* out                 = (float*)d_out;

    const int massSmem = (4 * T_ + 3 * 256 * 8) * 4;   // 57344 bytes
    cudaFuncSetAttribute(mass_kernel,
                         cudaFuncAttributeMaxDynamicSharedMemorySize, massSmem);
    cudaFuncSetAttribute(mlp_mma,
                         cudaFuncAttributeMaxDynamicSharedMemorySize, 65536);

    len_kernel<<<B_, 256>>>(mask);
    prep_kernel<<<(B_ * T_) / 256, 256>>>(tokens);
    w2t_kernel<<<(D_ * H_) / 256, 256>>>(W2);
    mass_kernel<<<dim3(T_ / 32, B_), 256, massSmem>>>();
    h_kernel<<<(B_ * T_) / 256, 256>>>(W1, b1);
    mlp_mma<<<(B_ * T_ / 128) * 4, 256, 65536>>>(b2, out);
}